// round 2
// baseline (speedup 1.0000x reference)
#include <cuda_runtime.h>
#include <cuda_bf16.h>
#include <cstddef>

typedef unsigned long long ull;
#define NEGF (-1e30f)

// ---------------- scratch (static device globals) ----------------
#define DCBUF (2*2048*512)
__device__ int   g_encTok[64 * 64];
__device__ int   g_segs[2 * 2048 * 3];
__device__ int   g_decTok[2 * 4 * 2048];
__device__ float g_zero[64 * 512];
__device__ float g_hid[64 * 64 * 512];
__device__ float g_encC[2 * 64 * 512];
__device__ float g_h0[2 * 2048 * 512];
__device__ float g_dc[2 * DCBUF];
__device__ float g_hs[2 * 4 * 2048 * 512];
__device__ float g_logZ[2 * 4 * 2048];
__device__ float g_gch[2 * 4 * 2048];
__device__ float g_gp[2 * 4 * 2048];

// ---------------- helpers ----------------
__device__ __forceinline__ float sigm_(float x) { return 1.f / (1.f + __expf(-x)); }
__device__ __forceinline__ ull splat2(float b) {
    ull r; asm("mov.b64 %0, {%1, %1};" : "=l"(r) : "f"(b)); return r;
}
__device__ __forceinline__ void ffma2(ull &acc, ull a, ull b) {
    asm("fma.rn.f32x2 %0, %1, %2, %0;" : "+l"(acc) : "l"(a), "l"(b));
}
__device__ __forceinline__ float2 unpack2(ull v) {
    float2 r; asm("mov.b64 {%0, %1}, %2;" : "=f"(r.x), "=f"(r.y) : "l"(v)); return r;
}
__device__ __forceinline__ void lse_upd(float x, float &m, float &s) {
    float d = x - m;
    if (d > 0.f) { s = s * __expf(-d) + 1.f; m = x; }
    else         { s += __expf(d); }
}

// ---------------- prep ----------------
__global__ void prep_kernel(const int* __restrict__ sent) {
    int tid = blockIdx.x * blockDim.x + threadIdx.x;
    int nthr = gridDim.x * blockDim.x;
    for (int i = tid; i < 64 * 64; i += nthr) {
        int t = i >> 6, n = i & 63;
        int v = 0;
        if (t > 0) {
            int b = n & 31;
            v = (n < 32) ? sent[b * 64 + t - 1] : sent[b * 64 + 64 - t];
        }
        g_encTok[i] = v;
    }
    for (int i = tid; i < 2 * 2048; i += nthr) {
        int dir = i >> 11, r = i & 2047;
        int t = r >> 5, b = r & 31;
        int sg[3];
#pragma unroll
        for (int w = 0; w < 3; ++w) {
            int p = min(t + w, 63);
            sg[w] = (dir == 0) ? sent[b * 64 + p] : sent[b * 64 + 63 - p];
            g_segs[i * 3 + w] = sg[w];
        }
        g_decTok[(dir * 4 + 0) * 2048 + r] = 0;
#pragma unroll
        for (int s2 = 1; s2 < 4; ++s2) g_decTok[(dir * 4 + s2) * 2048 + r] = sg[s2 - 1];
    }
    for (int i = tid; i < 64 * 512; i += nthr) g_zero[i] = 0.f;
}

// ---------------- h0 init for decoders ----------------
__global__ void h0_init_kernel() {
    int i = blockIdx.x * blockDim.x + threadIdx.x;   // 0 .. 2*2048*512-1
    int h = i & 511;
    int rr = i >> 9;            // 0..4095
    int r = rr & 2047, dir = rr >> 11;
    int t = r >> 5, b = r & 31;
    g_h0[i] = g_hid[((size_t)t * 64 + dir * 32 + b) * 512 + h];
}

// ---------------- fused LSTM step ----------------
// phase 0: encoder (M=64, step=t, grid (2,16,1))
// phase 1: decoder (M=2048/dir, step=s, grid (64,16,2))
// Block: 32 rows x 32 hidden cols (=128 gate cols). 256 threads (16x16),
// thread tile: 2 rows x 8 gate cols, f32x2 packed over col pairs.
__global__ void __launch_bounds__(256) lstm_step(
    const float* __restrict__ emb,
    const float* __restrict__ Wih0, const float* __restrict__ Whh0, const float* __restrict__ b0,
    const float* __restrict__ Wih1, const float* __restrict__ Whh1, const float* __restrict__ b1,
    int phase, int step)
{
    const int dir = blockIdx.z;
    const float* Wih = dir ? Wih1 : Wih0;
    const float* Whh = dir ? Whh1 : Whh0;
    const float* bias = dir ? b1 : b0;

    const int* tok; const float *h_in, *c_in; float *h_out, *c_out;
    if (phase == 0) {
        tok  = g_encTok + step * 64;
        h_in = step ? g_hid + (size_t)(step - 1) * 64 * 512 : g_zero;
        c_in = step ? g_encC + (size_t)((step - 1) & 1) * 64 * 512 : g_zero;
        h_out = g_hid + (size_t)step * 64 * 512;
        c_out = g_encC + (size_t)(step & 1) * 64 * 512;
    } else {
        tok  = g_decTok + (dir * 4 + step) * 2048;
        h_in = step ? g_hs + ((size_t)(dir * 4 + step - 1)) * 2048 * 512
                    : g_h0 + (size_t)dir * 2048 * 512;
        c_in = step ? g_dc + (size_t)((step - 1) & 1) * DCBUF + (size_t)dir * 2048 * 512
                    : g_h0 + (size_t)dir * 2048 * 512;
        h_out = g_hs + ((size_t)(dir * 4 + step)) * 2048 * 512;
        c_out = g_dc + (size_t)(step & 1) * DCBUF + (size_t)dir * 2048 * 512;
    }

    __shared__ __align__(16) float As[16][32];
    __shared__ __align__(16) float Ws[16][128];
    __shared__ float Gs[32][132];

    const int tid = threadIdx.x;
    const int r0 = blockIdx.x * 32;
    const int c0 = blockIdx.y * 32;
    const int tx = tid & 15, ty = tid >> 4;

    // A loader
    const int la_r = tid & 31;
    const int la_k = (tid >> 5) * 2;
    const int mytok = tok[r0 + la_r];
    const float* aE = emb + (size_t)mytok * 256;
    const float* aH = h_in + (size_t)(r0 + la_r) * 512 - 256;

    // W loader
    const int lw_j = tid >> 1;
    const int lw_k = (tid & 1) * 8;
    const int wrow = (lw_j >> 5) * 512 + c0 + (lw_j & 31);
    const float* wI = Wih + (size_t)wrow * 256;
    const float* wH = Whh + (size_t)wrow * 512 - 256;

    ull acc[2][4];
#pragma unroll
    for (int p = 0; p < 2; ++p)
#pragma unroll
        for (int c = 0; c < 4; ++c) acc[p][c] = 0ull;

    for (int k0 = 0; k0 < 768; k0 += 16) {
        {
            const float* s = (k0 < 256 ? aE : aH) + k0 + la_k;
            float2 v = *(const float2*)s;
            As[la_k][la_r] = v.x; As[la_k + 1][la_r] = v.y;
        }
        {
            const float* s = (k0 < 256 ? wI : wH) + k0 + lw_k;
            float4 v0 = *(const float4*)s;
            float4 v1 = *(const float4*)(s + 4);
            Ws[lw_k+0][lw_j]=v0.x; Ws[lw_k+1][lw_j]=v0.y; Ws[lw_k+2][lw_j]=v0.z; Ws[lw_k+3][lw_j]=v0.w;
            Ws[lw_k+4][lw_j]=v1.x; Ws[lw_k+5][lw_j]=v1.y; Ws[lw_k+6][lw_j]=v1.z; Ws[lw_k+7][lw_j]=v1.w;
        }
        __syncthreads();
#pragma unroll
        for (int k = 0; k < 16; ++k) {
            float2 av = *(const float2*)&As[k][ty * 2];
            ull a0 = splat2(av.x), a1 = splat2(av.y);
            longlong2 b01 = *(const longlong2*)&Ws[k][tx * 8];
            longlong2 b23 = *(const longlong2*)&Ws[k][tx * 8 + 4];
            ffma2(acc[0][0], a0, (ull)b01.x); ffma2(acc[1][0], a1, (ull)b01.x);
            ffma2(acc[0][1], a0, (ull)b01.y); ffma2(acc[1][1], a1, (ull)b01.y);
            ffma2(acc[0][2], a0, (ull)b23.x); ffma2(acc[1][2], a1, (ull)b23.x);
            ffma2(acc[0][3], a0, (ull)b23.y); ffma2(acc[1][3], a1, (ull)b23.y);
        }
        __syncthreads();
    }

    // gates (+bias) into smem
#pragma unroll
    for (int cp = 0; cp < 4; ++cp) {
        float2 v0 = unpack2(acc[0][cp]);
        float2 v1 = unpack2(acc[1][cp]);
        int j0 = tx * 8 + 2 * cp;
#pragma unroll
        for (int u = 0; u < 2; ++u) {
            int j = j0 + u;
            float bb = bias[(j >> 5) * 512 + c0 + (j & 31)];
            float x0 = (u == 0 ? v0.x : v0.y);
            float x1 = (u == 0 ? v1.x : v1.y);
            Gs[ty * 2 + 0][j] = x0 + bb;
            Gs[ty * 2 + 1][j] = x1 + bb;
        }
    }
    __syncthreads();

    // cell update
    int row = tid >> 3, hc0 = (tid & 7) * 4;
#pragma unroll
    for (int q = 0; q < 4; ++q) {
        int hc = hc0 + q;
        float gi = Gs[row][hc];
        float gf = Gs[row][32 + hc];
        float gg = Gs[row][64 + hc];
        float go = Gs[row][96 + hc];
        size_t oi = (size_t)(r0 + row) * 512 + c0 + hc;
        float cprev = c_in[oi];
        float c = sigm_(gf) * cprev + sigm_(gi) * tanhf(gg);
        float h = sigm_(go) * tanhf(c);
        c_out[oi] = c;
        h_out[oi] = h;
    }
}

// ---------------- projection + online logsumexp + gathers ----------------
// Grid (128, 2): 64 rows per block over M=8192 (=4 steps x 2048), dir = blockIdx.y.
// A (64x512) resident in smem. 256 threads (16x16), thread: 4 rows x 8 cols.
__global__ void __launch_bounds__(256) proj_kernel(
    const float* __restrict__ hW0, const float* __restrict__ hb0,
    const float* __restrict__ hW1, const float* __restrict__ hb1)
{
    extern __shared__ float sm[];
    float (*As)[64]  = (float(*)[64])sm;                 // [512][64]
    float (*Ws)[128] = (float(*)[128])(sm + 512 * 64);   // [16][128]
    float* sg_ch = sm + 512 * 64 + 16 * 128;             // [64]
    float* sg_p  = sg_ch + 64;                           // [64]

    const int dir = blockIdx.y;
    const float* hW = dir ? hW1 : hW0;
    const float* hb = dir ? hb1 : hb0;
    const int tid = threadIdx.x;
    const int tx = tid & 15, ty = tid >> 4;
    const int row0 = blockIdx.x * 64;

    const float* hsBase = g_hs + (size_t)dir * 4 * 2048 * 512;
    {
        int r = tid & 63;
        int kq = (tid >> 6) * 4;
        const float* src = hsBase + (size_t)(row0 + r) * 512;
        for (int k0 = 0; k0 < 512; k0 += 16) {
            float4 v = *(const float4*)(src + k0 + kq);
            As[k0+kq+0][r]=v.x; As[k0+kq+1][r]=v.y; As[k0+kq+2][r]=v.z; As[k0+kq+3][r]=v.w;
        }
    }
    if (tid < 64) { sg_ch[tid] = 0.f; sg_p[tid] = 0.f; }
    __syncthreads();

    int ytok[4];
#pragma unroll
    for (int p = 0; p < 4; ++p) {
        int rg = row0 + ty * 4 + p;
        int s = rg >> 11, r = rg & 2047;
        ytok[p] = (s < 3) ? g_segs[(dir * 2048 + r) * 3 + s] : 0;
    }

    float m[4], ssum[4];
#pragma unroll
    for (int p = 0; p < 4; ++p) { m[p] = NEGF; ssum[p] = 0.f; }

    const int lw_j = tid >> 1;
    const int lw_k = (tid & 1) * 8;

    for (int v0 = 0; v0 < 8000; v0 += 128) {
        ull acc[4][4];
#pragma unroll
        for (int p = 0; p < 4; ++p)
#pragma unroll
            for (int c = 0; c < 4; ++c) acc[p][c] = 0ull;

        for (int k0 = 0; k0 < 512; k0 += 16) {
            {
                int vr = v0 + lw_j; if (vr > 7999) vr = 7999;
                const float* s = hW + (size_t)vr * 512 + k0 + lw_k;
                float4 a = *(const float4*)s;
                float4 b = *(const float4*)(s + 4);
                Ws[lw_k+0][lw_j]=a.x; Ws[lw_k+1][lw_j]=a.y; Ws[lw_k+2][lw_j]=a.z; Ws[lw_k+3][lw_j]=a.w;
                Ws[lw_k+4][lw_j]=b.x; Ws[lw_k+5][lw_j]=b.y; Ws[lw_k+6][lw_j]=b.z; Ws[lw_k+7][lw_j]=b.w;
            }
            __syncthreads();
#pragma unroll
            for (int k = 0; k < 16; ++k) {
                float4 av = *(const float4*)&As[k0 + k][ty * 4];
                ull a0 = splat2(av.x), a1 = splat2(av.y), a2 = splat2(av.z), a3 = splat2(av.w);
                longlong2 b01 = *(const longlong2*)&Ws[k][tx * 8];
                longlong2 b23 = *(const longlong2*)&Ws[k][tx * 8 + 4];
                ffma2(acc[0][0], a0, (ull)b01.x); ffma2(acc[1][0], a1, (ull)b01.x);
                ffma2(acc[2][0], a2, (ull)b01.x); ffma2(acc[3][0], a3, (ull)b01.x);
                ffma2(acc[0][1], a0, (ull)b01.y); ffma2(acc[1][1], a1, (ull)b01.y);
                ffma2(acc[2][1], a2, (ull)b01.y); ffma2(acc[3][1], a3, (ull)b01.y);
                ffma2(acc[0][2], a0, (ull)b23.x); ffma2(acc[1][2], a1, (ull)b23.x);
                ffma2(acc[2][2], a2, (ull)b23.x); ffma2(acc[3][2], a3, (ull)b23.x);
                ffma2(acc[0][3], a0, (ull)b23.y); ffma2(acc[1][3], a1, (ull)b23.y);
                ffma2(acc[2][3], a2, (ull)b23.y); ffma2(acc[3][3], a3, (ull)b23.y);
            }
            __syncthreads();
        }
        // chunk epilogue: bias, lse update, gathers
#pragma unroll
        for (int cp = 0; cp < 4; ++cp) {
            int vbase = v0 + tx * 8 + 2 * cp;
#pragma unroll
            for (int u = 0; u < 2; ++u) {
                int v = vbase + u;
                if (v < 8000) {
                    float bb = hb[v];
#pragma unroll
                    for (int p = 0; p < 4; ++p) {
                        float2 two = unpack2(acc[p][cp]);
                        float lg = (u == 0 ? two.x : two.y) + bb;
                        lse_upd(lg, m[p], ssum[p]);
                        if (v == ytok[p]) sg_ch[ty * 4 + p] = lg;
                        if (v == 0)      sg_p[ty * 4 + p]  = lg;
                    }
                }
            }
        }
    }

    // reduce (m,ssum) across the 16 tx lanes (within half-warps)
#pragma unroll
    for (int p = 0; p < 4; ++p) {
#pragma unroll
        for (int off = 8; off; off >>= 1) {
            float om = __shfl_xor_sync(0xffffffffu, m[p], off);
            float os = __shfl_xor_sync(0xffffffffu, ssum[p], off);
            float M = fmaxf(m[p], om);
            ssum[p] = ssum[p] * __expf(m[p] - M) + os * __expf(om - M);
            m[p] = M;
        }
    }
    __syncthreads();
    if (tx == 0) {
#pragma unroll
        for (int p = 0; p < 4; ++p) {
            int rg = row0 + ty * 4 + p;
            int s = rg >> 11, r = rg & 2047;
            int idx = (dir * 4 + s) * 2048 + r;
            g_logZ[idx] = m[p] + logf(ssum[p]);
            g_gch[idx]  = sg_ch[ty * 4 + p];
            g_gp[idx]   = sg_p[ty * 4 + p];
        }
    }
}

// ---------------- final DP ----------------
__device__ __forceinline__ float seg_score(int dir, int t, int l, int b) {
    int r = t * 32 + b;
    float acc = 0.f;
    for (int s = 0; s <= l; ++s) {
        int idx = (dir * 4 + s) * 2048 + r;
        acc += g_gch[idx] - g_logZ[idx];
    }
    int idx = (dir * 4 + l + 1) * 2048 + r;
    acc += g_gp[idx] - g_logZ[idx];
    return acc;
}

__global__ void dp_kernel(float* __restrict__ out) {
    int b = threadIdx.x;  // 0..31
    float buf0 = 0.f, buf1 = NEGF, buf2 = NEGF;
    for (int e = 0; e < 64; ++e) {
        float p[3];
#pragma unroll
        for (int l = 0; l < 3; ++l) {
            int start = e - l;
            if (start >= 0)
                p[l] = seg_score(0, start, l, b) + seg_score(1, 63 - e, l, b);
            else
                p[l] = NEGF;
        }
        float x0 = buf0 + p[0], x1 = buf1 + p[1], x2 = buf2 + p[2];
        float M = fmaxf(x0, fmaxf(x1, x2));
        float tot = M + logf(__expf(x0 - M) + __expf(x1 - M) + __expf(x2 - M));
        buf2 = buf1; buf1 = buf0; buf0 = tot;
    }
    float v = buf0;
#pragma unroll
    for (int off = 16; off; off >>= 1) v += __shfl_xor_sync(0xffffffffu, v, off);
    if (b == 0) out[0] = -v / 32.f;
}

// ---------------- launch ----------------
extern "C" void kernel_launch(void* const* d_in, const int* in_sizes, int n_in,
                              void* d_out, int out_size) {
    const int*   sent   = (const int*)  d_in[0];
    const float* emb    = (const float*)d_in[1];
    const float* eWih   = (const float*)d_in[2];
    const float* eWhh   = (const float*)d_in[3];
    const float* eb     = (const float*)d_in[4];
    const float* fWih   = (const float*)d_in[5];
    const float* fWhh   = (const float*)d_in[6];
    const float* fb     = (const float*)d_in[7];
    const float* fhW    = (const float*)d_in[8];
    const float* fhb    = (const float*)d_in[9];
    const float* bWih   = (const float*)d_in[10];
    const float* bWhh   = (const float*)d_in[11];
    const float* bb     = (const float*)d_in[12];
    const float* bhW    = (const float*)d_in[13];
    const float* bhb    = (const float*)d_in[14];

    cudaFuncSetAttribute(proj_kernel, cudaFuncAttributeMaxDynamicSharedMemorySize, 139776);

    prep_kernel<<<64, 256>>>(sent);

    for (int t = 0; t < 64; ++t)
        lstm_step<<<dim3(2, 16, 1), 256>>>(emb, eWih, eWhh, eb, eWih, eWhh, eb, 0, t);

    h0_init_kernel<<<8192, 256>>>();

    for (int s = 0; s < 4; ++s)
        lstm_step<<<dim3(64, 16, 2), 256>>>(emb, fWih, fWhh, fb, bWih, bWhh, bb, 1, s);

    proj_kernel<<<dim3(128, 2), 256, 139776>>>(fhW, fhb, bhW, bhb);

    dp_kernel<<<1, 32>>>((float*)d_out);
}

// round 3
// speedup vs baseline: 1.5519x; 1.5519x over previous
#include <cuda_runtime.h>
#include <cuda_bf16.h>
#include <cstddef>

typedef unsigned long long ull;
#define NEGF (-1e30f)

// ---------------- scratch ----------------
#define DCBUF (2*2048*512)
__device__ int   g_encTok[64 * 64];
__device__ int   g_segs[2 * 2048 * 3];
__device__ int   g_decTok[2 * 4 * 2048];
__device__ float g_hid[64 * 64 * 512];
__device__ float g_xw[64 * 64 * 2048];      // x·Wih^T for all encoder steps
__device__ float g_h0[2 * 2048 * 512];
__device__ float g_dc[2 * DCBUF];
__device__ float g_hs[2 * 4 * 2048 * 512];
__device__ float g_logZ[2 * 4 * 2048];
__device__ float g_gch[2 * 4 * 2048];
__device__ float g_gp[2 * 4 * 2048];
__device__ unsigned g_barCnt;

// ---------------- helpers ----------------
__device__ __forceinline__ float sigm_(float x) { return 1.f / (1.f + __expf(-x)); }
__device__ __forceinline__ ull splat2(float b) {
    ull r; asm("mov.b64 %0, {%1, %1};" : "=l"(r) : "f"(b)); return r;
}
__device__ __forceinline__ ull pack2(float x, float y) {
    ull r; asm("mov.b64 %0, {%1, %2};" : "=l"(r) : "f"(x), "f"(y)); return r;
}
__device__ __forceinline__ void ffma2(ull &acc, ull a, ull b) {
    asm("fma.rn.f32x2 %0, %1, %2, %0;" : "+l"(acc) : "l"(a), "l"(b));
}
__device__ __forceinline__ float2 unpack2(ull v) {
    float2 r; asm("mov.b64 {%0, %1}, %2;" : "=f"(r.x), "=f"(r.y) : "l"(v)); return r;
}
__device__ __forceinline__ void lse_upd(float x, float &m, float &s) {
    float d = x - m;
    if (d > 0.f) { s = s * __expf(-d) + 1.f; m = x; }
    else         { s += __expf(d); }
}

// ---------------- prep ----------------
__global__ void prep_kernel(const int* __restrict__ sent) {
    int tid = blockIdx.x * blockDim.x + threadIdx.x;
    int nthr = gridDim.x * blockDim.x;
    if (tid == 0) g_barCnt = 0u;
    for (int i = tid; i < 64 * 64; i += nthr) {
        int t = i >> 6, n = i & 63;
        int v = 0;
        if (t > 0) {
            int b = n & 31;
            v = (n < 32) ? sent[b * 64 + t - 1] : sent[b * 64 + 64 - t];
        }
        g_encTok[i] = v;
    }
    for (int i = tid; i < 2 * 2048; i += nthr) {
        int dir = i >> 11, r = i & 2047;
        int t = r >> 5, b = r & 31;
        int sg[3];
#pragma unroll
        for (int w = 0; w < 3; ++w) {
            int p = min(t + w, 63);
            sg[w] = (dir == 0) ? sent[b * 64 + p] : sent[b * 64 + 63 - p];
            g_segs[i * 3 + w] = sg[w];
        }
        g_decTok[(dir * 4 + 0) * 2048 + r] = 0;
#pragma unroll
        for (int s2 = 1; s2 < 4; ++s2) g_decTok[(dir * 4 + s2) * 2048 + r] = sg[s2 - 1];
    }
}

// ---------------- encoder x·Wih^T batched GEMM ----------------
// M=4096 (64 steps x 64 rows), K=256, N=2048. Grid (64,16), 256 thr, 4x8 tile.
__global__ void __launch_bounds__(256) xw_gemm(
    const float* __restrict__ emb, const float* __restrict__ Wih)
{
    __shared__ __align__(16) float As[16][64];
    __shared__ __align__(16) float Ws[16][128];

    const int tid = threadIdx.x;
    const int r0 = blockIdx.x * 64;
    const int g0 = blockIdx.y * 128;
    const int tx = tid & 15, ty = tid >> 4;

    const int la_r = tid & 63;
    const int la_q = (tid >> 6) * 4;
    const int mytok = g_encTok[r0 + la_r];
    const float* aE = emb + (size_t)mytok * 256;

    const int lw_j = tid >> 1;
    const int lw_k = (tid & 1) * 8;
    const float* wI = Wih + (size_t)(g0 + lw_j) * 256;

    ull acc[4][4];
#pragma unroll
    for (int p = 0; p < 4; ++p)
#pragma unroll
        for (int c = 0; c < 4; ++c) acc[p][c] = 0ull;

    for (int k0 = 0; k0 < 256; k0 += 16) {
        {
            float4 v = *(const float4*)(aE + k0 + la_q);
            As[la_q+0][la_r]=v.x; As[la_q+1][la_r]=v.y; As[la_q+2][la_r]=v.z; As[la_q+3][la_r]=v.w;
        }
        {
            const float* s = wI + k0 + lw_k;
            float4 a4 = *(const float4*)s;
            float4 b4 = *(const float4*)(s + 4);
            Ws[lw_k+0][lw_j]=a4.x; Ws[lw_k+1][lw_j]=a4.y; Ws[lw_k+2][lw_j]=a4.z; Ws[lw_k+3][lw_j]=a4.w;
            Ws[lw_k+4][lw_j]=b4.x; Ws[lw_k+5][lw_j]=b4.y; Ws[lw_k+6][lw_j]=b4.z; Ws[lw_k+7][lw_j]=b4.w;
        }
        __syncthreads();
#pragma unroll
        for (int k = 0; k < 16; ++k) {
            float4 av = *(const float4*)&As[k][ty * 4];
            ull a0 = splat2(av.x), a1 = splat2(av.y), a2 = splat2(av.z), a3 = splat2(av.w);
            longlong2 b01 = *(const longlong2*)&Ws[k][tx * 8];
            longlong2 b23 = *(const longlong2*)&Ws[k][tx * 8 + 4];
            ffma2(acc[0][0], a0, (ull)b01.x); ffma2(acc[1][0], a1, (ull)b01.x);
            ffma2(acc[2][0], a2, (ull)b01.x); ffma2(acc[3][0], a3, (ull)b01.x);
            ffma2(acc[0][1], a0, (ull)b01.y); ffma2(acc[1][1], a1, (ull)b01.y);
            ffma2(acc[2][1], a2, (ull)b01.y); ffma2(acc[3][1], a3, (ull)b01.y);
            ffma2(acc[0][2], a0, (ull)b23.x); ffma2(acc[1][2], a1, (ull)b23.x);
            ffma2(acc[2][2], a2, (ull)b23.x); ffma2(acc[3][2], a3, (ull)b23.x);
            ffma2(acc[0][3], a0, (ull)b23.y); ffma2(acc[1][3], a1, (ull)b23.y);
            ffma2(acc[2][3], a2, (ull)b23.y); ffma2(acc[3][3], a3, (ull)b23.y);
        }
        __syncthreads();
    }
#pragma unroll
    for (int p = 0; p < 4; ++p) {
        float2 c0v = unpack2(acc[p][0]), c1v = unpack2(acc[p][1]);
        float2 c2v = unpack2(acc[p][2]), c3v = unpack2(acc[p][3]);
        float* dst = g_xw + (size_t)(r0 + ty * 4 + p) * 2048 + g0 + tx * 8;
        *(float4*)dst       = make_float4(c0v.x, c0v.y, c1v.x, c1v.y);
        *(float4*)(dst + 4) = make_float4(c2v.x, c2v.y, c3v.x, c3v.y);
    }
}

// ---------------- persistent encoder recurrence ----------------
// grid=128 blocks (all co-resident), block owns 4 hidden cols -> 16 Whh rows in smem.
// Thread (r = tid>>2, hc = tid&3) computes all 4 gates of one (row, hidden col);
// c lives in a register across all 64 steps. One grid barrier per step.
__device__ __forceinline__ void gridbar(int step) {
    __syncthreads();
    if (threadIdx.x == 0) {
        __threadfence();
        unsigned target = 128u * (unsigned)(step + 1);
        atomicAdd(&g_barCnt, 1u);
        while (atomicAdd(&g_barCnt, 0u) < target) { }
    }
    __syncthreads();
}

__global__ void __launch_bounds__(256) enc_persist(
    const float* __restrict__ Whh, const float* __restrict__ bias)
{
    extern __shared__ char esm_raw[];
    ull*   sWif = (ull*)esm_raw;              // [512][4]
    ull*   sWgo = sWif + 512 * 4;             // [512][4]
    float* h_sm = (float*)(sWgo + 512 * 4);   // [64][132]

    const int tid = threadIdx.x;
    const int hc0 = blockIdx.x * 4;

    {   // load Whh slice, packed (i,f) and (g,o) per (k, hc)
        int hc = tid >> 6;
        int kb = (tid & 63) * 8;
        const float* wi = Whh + (size_t)(0 * 512 + hc0 + hc) * 512;
        const float* wf = Whh + (size_t)(1 * 512 + hc0 + hc) * 512;
        const float* wg = Whh + (size_t)(2 * 512 + hc0 + hc) * 512;
        const float* wo = Whh + (size_t)(3 * 512 + hc0 + hc) * 512;
#pragma unroll
        for (int k = kb; k < kb + 8; ++k) {
            sWif[k * 4 + hc] = pack2(wi[k], wf[k]);
            sWgo[k * 4 + hc] = pack2(wg[k], wo[k]);
        }
    }
    const int r  = tid >> 2;
    const int hc = tid & 3;
    const float bi = bias[0 * 512 + hc0 + hc];
    const float bf = bias[1 * 512 + hc0 + hc];
    const float bg = bias[2 * 512 + hc0 + hc];
    const float bo = bias[3 * 512 + hc0 + hc];
    float c = 0.f;
    __syncthreads();

    const int lr = tid & 63;
    const int lq = (tid >> 6) * 4;

    for (int t = 0; t < 64; ++t) {
        ull aif = 0ull, ago = 0ull;
        if (t > 0) {
            const float* hprev = g_hid + (size_t)(t - 1) * 64 * 512;
            for (int kc = 0; kc < 512; kc += 128) {
                {
                    const float* src = hprev + (size_t)lr * 512 + kc;
#pragma unroll
                    for (int q = lq; q < 128; q += 16)
                        *(float4*)&h_sm[lr * 132 + q] = *(const float4*)(src + q);
                }
                __syncthreads();
#pragma unroll
                for (int kq = 0; kq < 128; kq += 4) {
                    float4 a = *(const float4*)&h_sm[r * 132 + kq];
                    ull a0 = splat2(a.x), a1 = splat2(a.y), a2 = splat2(a.z), a3 = splat2(a.w);
                    int kb2 = (kc + kq) * 4 + hc;
                    ffma2(aif, a0, sWif[kb2 + 0]);  ffma2(ago, a0, sWgo[kb2 + 0]);
                    ffma2(aif, a1, sWif[kb2 + 4]);  ffma2(ago, a1, sWgo[kb2 + 4]);
                    ffma2(aif, a2, sWif[kb2 + 8]);  ffma2(ago, a2, sWgo[kb2 + 8]);
                    ffma2(aif, a3, sWif[kb2 + 12]); ffma2(ago, a3, sWgo[kb2 + 12]);
                }
                __syncthreads();
            }
        }
        const float* xw = g_xw + ((size_t)t * 64 + r) * 2048;
        float2 vif = unpack2(aif), vgo = unpack2(ago);
        float gi = vif.x + xw[0 * 512 + hc0 + hc] + bi;
        float gf = vif.y + xw[1 * 512 + hc0 + hc] + bf;
        float gg = vgo.x + xw[2 * 512 + hc0 + hc] + bg;
        float go = vgo.y + xw[3 * 512 + hc0 + hc] + bo;
        c = sigm_(gf) * c + sigm_(gi) * tanhf(gg);
        float h = sigm_(go) * tanhf(c);
        g_hid[((size_t)t * 64 + r) * 512 + hc0 + hc] = h;
        if (t < 63) gridbar(t);
    }
}

// ---------------- decoder h0 ----------------
__global__ void h0_init_kernel() {
    int i = blockIdx.x * blockDim.x + threadIdx.x;
    int h = i & 511;
    int rr = i >> 9;
    int r = rr & 2047, dir = rr >> 11;
    int t = r >> 5, b = r & 31;
    g_h0[i] = g_hid[((size_t)t * 64 + dir * 32 + b) * 512 + h];
}

// ---------------- decoder LSTM step: 64 rows x 128 gate cols, 4x8 tile ----------------
__global__ void __launch_bounds__(256) dec_step(
    const float* __restrict__ emb,
    const float* __restrict__ Wih0, const float* __restrict__ Whh0, const float* __restrict__ b0,
    const float* __restrict__ Wih1, const float* __restrict__ Whh1, const float* __restrict__ b1,
    int step)
{
    const int dir = blockIdx.z;
    const float* Wih = dir ? Wih1 : Wih0;
    const float* Whh = dir ? Whh1 : Whh0;
    const float* bias = dir ? b1 : b0;

    const int* tok = g_decTok + (dir * 4 + step) * 2048;
    const float* h_in = step ? g_hs + ((size_t)(dir * 4 + step - 1)) * 2048 * 512
                             : g_h0 + (size_t)dir * 2048 * 512;
    const float* c_in = step ? g_dc + (size_t)((step - 1) & 1) * DCBUF + (size_t)dir * 2048 * 512
                             : g_h0 + (size_t)dir * 2048 * 512;
    float* h_out = g_hs + ((size_t)(dir * 4 + step)) * 2048 * 512;
    float* c_out = g_dc + (size_t)(step & 1) * DCBUF + (size_t)dir * 2048 * 512;

    __shared__ __align__(16) float As[16][64];
    __shared__ __align__(16) float Ws[16][128];
    __shared__ float Gs[64][130];

    const int tid = threadIdx.x;
    const int r0 = blockIdx.x * 64;
    const int c0h = blockIdx.y * 32;
    const int tx = tid & 15, ty = tid >> 4;

    const int la_r = tid & 63;
    const int la_q = (tid >> 6) * 4;
    const int mytok = tok[r0 + la_r];
    const float* aE = emb + (size_t)mytok * 256;
    const float* aH = h_in + (size_t)(r0 + la_r) * 512 - 256;

    const int lw_j = tid >> 1;
    const int lw_k = (tid & 1) * 8;
    const int wrow = (lw_j >> 5) * 512 + c0h + (lw_j & 31);
    const float* wI = Wih + (size_t)wrow * 256;
    const float* wH = Whh + (size_t)wrow * 512 - 256;

    ull acc[4][4];
#pragma unroll
    for (int p = 0; p < 4; ++p)
#pragma unroll
        for (int c = 0; c < 4; ++c) acc[p][c] = 0ull;

    for (int k0 = 0; k0 < 768; k0 += 16) {
        {
            const float* s = (k0 < 256 ? aE : aH) + k0 + la_q;
            float4 v = *(const float4*)s;
            As[la_q+0][la_r]=v.x; As[la_q+1][la_r]=v.y; As[la_q+2][la_r]=v.z; As[la_q+3][la_r]=v.w;
        }
        {
            const float* s = (k0 < 256 ? wI : wH) + k0 + lw_k;
            float4 a4 = *(const float4*)s;
            float4 b4 = *(const float4*)(s + 4);
            Ws[lw_k+0][lw_j]=a4.x; Ws[lw_k+1][lw_j]=a4.y; Ws[lw_k+2][lw_j]=a4.z; Ws[lw_k+3][lw_j]=a4.w;
            Ws[lw_k+4][lw_j]=b4.x; Ws[lw_k+5][lw_j]=b4.y; Ws[lw_k+6][lw_j]=b4.z; Ws[lw_k+7][lw_j]=b4.w;
        }
        __syncthreads();
#pragma unroll
        for (int k = 0; k < 16; ++k) {
            float4 av = *(const float4*)&As[k][ty * 4];
            ull a0 = splat2(av.x), a1 = splat2(av.y), a2 = splat2(av.z), a3 = splat2(av.w);
            longlong2 b01 = *(const longlong2*)&Ws[k][tx * 8];
            longlong2 b23 = *(const longlong2*)&Ws[k][tx * 8 + 4];
            ffma2(acc[0][0], a0, (ull)b01.x); ffma2(acc[1][0], a1, (ull)b01.x);
            ffma2(acc[2][0], a2, (ull)b01.x); ffma2(acc[3][0], a3, (ull)b01.x);
            ffma2(acc[0][1], a0, (ull)b01.y); ffma2(acc[1][1], a1, (ull)b01.y);
            ffma2(acc[2][1], a2, (ull)b01.y); ffma2(acc[3][1], a3, (ull)b01.y);
            ffma2(acc[0][2], a0, (ull)b23.x); ffma2(acc[1][2], a1, (ull)b23.x);
            ffma2(acc[2][2], a2, (ull)b23.x); ffma2(acc[3][2], a3, (ull)b23.x);
            ffma2(acc[0][3], a0, (ull)b23.y); ffma2(acc[1][3], a1, (ull)b23.y);
            ffma2(acc[2][3], a2, (ull)b23.y); ffma2(acc[3][3], a3, (ull)b23.y);
        }
        __syncthreads();
    }

#pragma unroll
    for (int cp = 0; cp < 4; ++cp) {
        float2 v[4];
#pragma unroll
        for (int p = 0; p < 4; ++p) v[p] = unpack2(acc[p][cp]);
        int j0 = tx * 8 + 2 * cp;
#pragma unroll
        for (int u = 0; u < 2; ++u) {
            int j = j0 + u;
            float bb = bias[(j >> 5) * 512 + c0h + (j & 31)];
#pragma unroll
            for (int p = 0; p < 4; ++p)
                Gs[ty * 4 + p][j] = (u == 0 ? v[p].x : v[p].y) + bb;
        }
    }
    __syncthreads();

    {   // cell update: row = tid>>2, 8 hidden cols
        int row = tid >> 2;
        int hq = (tid & 3) * 8;
        size_t base = (size_t)(r0 + row) * 512 + c0h + hq;
#pragma unroll
        for (int q = 0; q < 8; ++q) {
            int hcj = hq + q;
            float gi = Gs[row][hcj];
            float gf = Gs[row][32 + hcj];
            float gg = Gs[row][64 + hcj];
            float go = Gs[row][96 + hcj];
            float cp2 = c_in[base + q];
            float cc = sigm_(gf) * cp2 + sigm_(gi) * tanhf(gg);
            float hh = sigm_(go) * tanhf(cc);
            c_out[base + q] = cc;
            h_out[base + q] = hh;
        }
    }
}

// ---------------- projection + online logsumexp + gathers ----------------
__global__ void __launch_bounds__(256) proj_kernel(
    const float* __restrict__ hW0, const float* __restrict__ hb0,
    const float* __restrict__ hW1, const float* __restrict__ hb1)
{
    extern __shared__ float sm[];
    float (*As)[64]  = (float(*)[64])sm;                 // [512][64]
    float (*Ws)[128] = (float(*)[128])(sm + 512 * 64);   // [16][128]
    float* sg_ch = sm + 512 * 64 + 16 * 128;
    float* sg_p  = sg_ch + 64;

    const int dir = blockIdx.y;
    const float* hW = dir ? hW1 : hW0;
    const float* hb = dir ? hb1 : hb0;
    const int tid = threadIdx.x;
    const int tx = tid & 15, ty = tid >> 4;
    const int row0 = blockIdx.x * 64;

    const float* hsBase = g_hs + (size_t)dir * 4 * 2048 * 512;
    {
        int r = tid & 63;
        int kq = (tid >> 6) * 4;
        const float* src = hsBase + (size_t)(row0 + r) * 512;
        for (int k0 = 0; k0 < 512; k0 += 16) {
            float4 v = *(const float4*)(src + k0 + kq);
            As[k0+kq+0][r]=v.x; As[k0+kq+1][r]=v.y; As[k0+kq+2][r]=v.z; As[k0+kq+3][r]=v.w;
        }
    }
    if (tid < 64) { sg_ch[tid] = 0.f; sg_p[tid] = 0.f; }
    __syncthreads();

    int ytok[4];
#pragma unroll
    for (int p = 0; p < 4; ++p) {
        int rg = row0 + ty * 4 + p;
        int s = rg >> 11, r = rg & 2047;
        ytok[p] = (s < 3) ? g_segs[(dir * 2048 + r) * 3 + s] : 0;
    }

    float m[4], ssum[4];
#pragma unroll
    for (int p = 0; p < 4; ++p) { m[p] = NEGF; ssum[p] = 0.f; }

    const int lw_j = tid >> 1;
    const int lw_k = (tid & 1) * 8;

    for (int v0 = 0; v0 < 8000; v0 += 128) {
        ull acc[4][4];
#pragma unroll
        for (int p = 0; p < 4; ++p)
#pragma unroll
            for (int c = 0; c < 4; ++c) acc[p][c] = 0ull;

        for (int k0 = 0; k0 < 512; k0 += 16) {
            {
                int vr = v0 + lw_j; if (vr > 7999) vr = 7999;
                const float* s = hW + (size_t)vr * 512 + k0 + lw_k;
                float4 a = *(const float4*)s;
                float4 b = *(const float4*)(s + 4);
                Ws[lw_k+0][lw_j]=a.x; Ws[lw_k+1][lw_j]=a.y; Ws[lw_k+2][lw_j]=a.z; Ws[lw_k+3][lw_j]=a.w;
                Ws[lw_k+4][lw_j]=b.x; Ws[lw_k+5][lw_j]=b.y; Ws[lw_k+6][lw_j]=b.z; Ws[lw_k+7][lw_j]=b.w;
            }
            __syncthreads();
#pragma unroll
            for (int k = 0; k < 16; ++k) {
                float4 av = *(const float4*)&As[k0 + k][ty * 4];
                ull a0 = splat2(av.x), a1 = splat2(av.y), a2 = splat2(av.z), a3 = splat2(av.w);
                longlong2 b01 = *(const longlong2*)&Ws[k][tx * 8];
                longlong2 b23 = *(const longlong2*)&Ws[k][tx * 8 + 4];
                ffma2(acc[0][0], a0, (ull)b01.x); ffma2(acc[1][0], a1, (ull)b01.x);
                ffma2(acc[2][0], a2, (ull)b01.x); ffma2(acc[3][0], a3, (ull)b01.x);
                ffma2(acc[0][1], a0, (ull)b01.y); ffma2(acc[1][1], a1, (ull)b01.y);
                ffma2(acc[2][1], a2, (ull)b01.y); ffma2(acc[3][1], a3, (ull)b01.y);
                ffma2(acc[0][2], a0, (ull)b23.x); ffma2(acc[1][2], a1, (ull)b23.x);
                ffma2(acc[2][2], a2, (ull)b23.x); ffma2(acc[3][2], a3, (ull)b23.x);
                ffma2(acc[0][3], a0, (ull)b23.y); ffma2(acc[1][3], a1, (ull)b23.y);
                ffma2(acc[2][3], a2, (ull)b23.y); ffma2(acc[3][3], a3, (ull)b23.y);
            }
            __syncthreads();
        }
#pragma unroll
        for (int cp = 0; cp < 4; ++cp) {
            int vbase = v0 + tx * 8 + 2 * cp;
#pragma unroll
            for (int u = 0; u < 2; ++u) {
                int v = vbase + u;
                if (v < 8000) {
                    float bb = hb[v];
#pragma unroll
                    for (int p = 0; p < 4; ++p) {
                        float2 two = unpack2(acc[p][cp]);
                        float lg = (u == 0 ? two.x : two.y) + bb;
                        lse_upd(lg, m[p], ssum[p]);
                        if (v == ytok[p]) sg_ch[ty * 4 + p] = lg;
                        if (v == 0)       sg_p[ty * 4 + p]  = lg;
                    }
                }
            }
        }
    }

#pragma unroll
    for (int p = 0; p < 4; ++p) {
#pragma unroll
        for (int off = 8; off; off >>= 1) {
            float om = __shfl_xor_sync(0xffffffffu, m[p], off);
            float os = __shfl_xor_sync(0xffffffffu, ssum[p], off);
            float M = fmaxf(m[p], om);
            ssum[p] = ssum[p] * __expf(m[p] - M) + os * __expf(om - M);
            m[p] = M;
        }
    }
    __syncthreads();
    if (tx == 0) {
#pragma unroll
        for (int p = 0; p < 4; ++p) {
            int rg = row0 + ty * 4 + p;
            int s = rg >> 11, r = rg & 2047;
            int idx = (dir * 4 + s) * 2048 + r;
            g_logZ[idx] = m[p] + logf(ssum[p]);
            g_gch[idx]  = sg_ch[ty * 4 + p];
            g_gp[idx]   = sg_p[ty * 4 + p];
        }
    }
}

// ---------------- final DP ----------------
__device__ __forceinline__ float seg_score(int dir, int t, int l, int b) {
    int r = t * 32 + b;
    float acc = 0.f;
    for (int s = 0; s <= l; ++s) {
        int idx = (dir * 4 + s) * 2048 + r;
        acc += g_gch[idx] - g_logZ[idx];
    }
    int idx = (dir * 4 + l + 1) * 2048 + r;
    acc += g_gp[idx] - g_logZ[idx];
    return acc;
}

__global__ void dp_kernel(float* __restrict__ out) {
    int b = threadIdx.x;
    float buf0 = 0.f, buf1 = NEGF, buf2 = NEGF;
    for (int e = 0; e < 64; ++e) {
        float p[3];
#pragma unroll
        for (int l = 0; l < 3; ++l) {
            int start = e - l;
            p[l] = (start >= 0)
                 ? seg_score(0, start, l, b) + seg_score(1, 63 - e, l, b)
                 : NEGF;
        }
        float x0 = buf0 + p[0], x1 = buf1 + p[1], x2 = buf2 + p[2];
        float M = fmaxf(x0, fmaxf(x1, x2));
        float tot = M + logf(__expf(x0 - M) + __expf(x1 - M) + __expf(x2 - M));
        buf2 = buf1; buf1 = buf0; buf0 = tot;
    }
    float v = buf0;
#pragma unroll
    for (int off = 16; off; off >>= 1) v += __shfl_xor_sync(0xffffffffu, v, off);
    if (b == 0) out[0] = -v / 32.f;
}

// ---------------- launch ----------------
extern "C" void kernel_launch(void* const* d_in, const int* in_sizes, int n_in,
                              void* d_out, int out_size) {
    const int*   sent = (const int*)  d_in[0];
    const float* emb  = (const float*)d_in[1];
    const float* eWih = (const float*)d_in[2];
    const float* eWhh = (const float*)d_in[3];
    const float* eb   = (const float*)d_in[4];
    const float* fWih = (const float*)d_in[5];
    const float* fWhh = (const float*)d_in[6];
    const float* fb   = (const float*)d_in[7];
    const float* fhW  = (const float*)d_in[8];
    const float* fhb  = (const float*)d_in[9];
    const float* bWih = (const float*)d_in[10];
    const float* bWhh = (const float*)d_in[11];
    const float* bb   = (const float*)d_in[12];
    const float* bhW  = (const float*)d_in[13];
    const float* bhb  = (const float*)d_in[14];

    cudaFuncSetAttribute(proj_kernel,  cudaFuncAttributeMaxDynamicSharedMemorySize, 139776);
    cudaFuncSetAttribute(enc_persist,  cudaFuncAttributeMaxDynamicSharedMemorySize, 66560);

    prep_kernel<<<64, 256>>>(sent);
    xw_gemm<<<dim3(64, 16), 256>>>(emb, eWih);
    enc_persist<<<128, 256, 66560>>>(eWhh, eb);
    h0_init_kernel<<<8192, 256>>>();
    for (int s = 0; s < 4; ++s)
        dec_step<<<dim3(32, 16, 2), 256>>>(emb, fWih, fWhh, fb, bWih, bWhh, bb, s);
    proj_kernel<<<dim3(128, 2), 256, 139776>>>(fhW, fhb, bhW, bhb);
    dp_kernel<<<1, 32>>>((float*)d_out);
}

// round 5
// speedup vs baseline: 3.5266x; 2.2724x over previous
#include <cuda_runtime.h>
#include <cuda_bf16.h>
#include <cstddef>
#include <cstdint>

typedef unsigned long long ull;
#define NEGF (-1e30f)

// ---------------- scratch ----------------
#define DCBUF (2*2048*512)
__device__ int   g_encTok[64 * 64];
__device__ int   g_segs[2 * 2048 * 3];
__device__ int   g_decTok[2 * 4 * 2048];
__device__ float g_hid[64 * 64 * 512];
__device__ float g_xw[64 * 64 * 2048];
__device__ float g_h0[2 * 2048 * 512];
__device__ float g_dc[2 * DCBUF];
__device__ float g_hs[2 * 4 * 2048 * 512];
__device__ __nv_bfloat16 g_hsb[2 * 4 * 2048 * 512];   // bf16 copy of decoder h
__device__ __nv_bfloat16 g_hWb[2 * 8064 * 512];       // bf16 hW, padded to 8064 rows
__device__ float g_logZ[2 * 4 * 2048];
__device__ float g_gch[2 * 4 * 2048];
__device__ float g_gp[2 * 4 * 2048];
__device__ unsigned g_barCnt;

// ---------------- helpers ----------------
__device__ __forceinline__ float sigm_(float x) { return 1.f / (1.f + __expf(-x)); }
__device__ __forceinline__ ull splat2(float b) {
    ull r; asm("mov.b64 %0, {%1, %1};" : "=l"(r) : "f"(b)); return r;
}
__device__ __forceinline__ ull pack2(float x, float y) {
    ull r; asm("mov.b64 %0, {%1, %2};" : "=l"(r) : "f"(x), "f"(y)); return r;
}
__device__ __forceinline__ void ffma2(ull &acc, ull a, ull b) {
    asm("fma.rn.f32x2 %0, %1, %2, %0;" : "+l"(acc) : "l"(a), "l"(b));
}
__device__ __forceinline__ float2 unpack2(ull v) {
    float2 r; asm("mov.b64 {%0, %1}, %2;" : "=f"(r.x), "=f"(r.y) : "l"(v)); return r;
}
__device__ __forceinline__ void lse_upd(float x, float &m, float &s) {
    float d = x - m;
    if (d > 0.f) { s = s * __expf(-d) + 1.f; m = x; }
    else         { s += __expf(d); }
}
__device__ __forceinline__ uint32_t smem_u32(const void* p) {
    uint32_t a;
    asm("{ .reg .u64 t; cvta.to.shared.u64 t, %1; cvt.u32.u64 %0, t; }" : "=r"(a) : "l"(p));
    return a;
}
__device__ __forceinline__ void ldsm4(uint32_t* r, uint32_t addr) {
    asm volatile("ldmatrix.sync.aligned.m8n8.x4.shared.b16 {%0,%1,%2,%3}, [%4];"
        : "=r"(r[0]), "=r"(r[1]), "=r"(r[2]), "=r"(r[3]) : "r"(addr));
}
__device__ __forceinline__ void mma_bf16(float* d, const uint32_t* a, const uint32_t* b) {
    asm volatile(
        "mma.sync.aligned.m16n8k16.row.col.f32.bf16.bf16.f32 "
        "{%0,%1,%2,%3}, {%4,%5,%6,%7}, {%8,%9}, {%0,%1,%2,%3};"
        : "+f"(d[0]), "+f"(d[1]), "+f"(d[2]), "+f"(d[3])
        : "r"(a[0]), "r"(a[1]), "r"(a[2]), "r"(a[3]), "r"(b[0]), "r"(b[1]));
}

// ---------------- prep ----------------
__global__ void prep_kernel(const int* __restrict__ sent) {
    int tid = blockIdx.x * blockDim.x + threadIdx.x;
    int nthr = gridDim.x * blockDim.x;
    if (tid == 0) g_barCnt = 0u;
    for (int i = tid; i < 64 * 64; i += nthr) {
        int t = i >> 6, n = i & 63;
        int v = 0;
        if (t > 0) {
            int b = n & 31;
            v = (n < 32) ? sent[b * 64 + t - 1] : sent[b * 64 + 64 - t];
        }
        g_encTok[i] = v;
    }
    for (int i = tid; i < 2 * 2048; i += nthr) {
        int dir = i >> 11, r = i & 2047;
        int t = r >> 5, b = r & 31;
        int sg[3];
#pragma unroll
        for (int w = 0; w < 3; ++w) {
            int p = min(t + w, 63);
            sg[w] = (dir == 0) ? sent[b * 64 + p] : sent[b * 64 + 63 - p];
            g_segs[i * 3 + w] = sg[w];
        }
        g_decTok[(dir * 4 + 0) * 2048 + r] = 0;
#pragma unroll
        for (int s2 = 1; s2 < 4; ++s2) g_decTok[(dir * 4 + s2) * 2048 + r] = sg[s2 - 1];
    }
}

// ---------------- hW -> bf16 (padded to 8064 rows) ----------------
__global__ void cvt_hw(const float* __restrict__ hW0, const float* __restrict__ hW1) {
    size_t i = (size_t)blockIdx.x * blockDim.x + threadIdx.x;
    if (i >= 2ull * 8064 * 512) return;
    int dir = (int)(i / (8064ull * 512));
    size_t rem = i % (8064ull * 512);
    int row = (int)(rem >> 9), k = (int)(rem & 511);
    const float* w = dir ? hW1 : hW0;
    float v = (row < 8000) ? w[(size_t)row * 512 + k] : 0.f;
    g_hWb[i] = __float2bfloat16(v);
}

// ---------------- encoder x·Wih^T batched GEMM ----------------
__global__ void __launch_bounds__(256) xw_gemm(
    const float* __restrict__ emb, const float* __restrict__ Wih)
{
    __shared__ __align__(16) float As[16][64];
    __shared__ __align__(16) float Ws[16][128];
    const int tid = threadIdx.x;
    const int r0 = blockIdx.x * 64;
    const int g0 = blockIdx.y * 128;
    const int tx = tid & 15, ty = tid >> 4;
    const int la_r = tid & 63;
    const int la_q = (tid >> 6) * 4;
    const int mytok = g_encTok[r0 + la_r];
    const float* aE = emb + (size_t)mytok * 256;
    const int lw_j = tid >> 1;
    const int lw_k = (tid & 1) * 8;
    const float* wI = Wih + (size_t)(g0 + lw_j) * 256;

    ull acc[4][4];
#pragma unroll
    for (int p = 0; p < 4; ++p)
#pragma unroll
        for (int c = 0; c < 4; ++c) acc[p][c] = 0ull;

    for (int k0 = 0; k0 < 256; k0 += 16) {
        {
            float4 v = *(const float4*)(aE + k0 + la_q);
            As[la_q+0][la_r]=v.x; As[la_q+1][la_r]=v.y; As[la_q+2][la_r]=v.z; As[la_q+3][la_r]=v.w;
        }
        {
            const float* s = wI + k0 + lw_k;
            float4 a4 = *(const float4*)s;
            float4 b4 = *(const float4*)(s + 4);
            Ws[lw_k+0][lw_j]=a4.x; Ws[lw_k+1][lw_j]=a4.y; Ws[lw_k+2][lw_j]=a4.z; Ws[lw_k+3][lw_j]=a4.w;
            Ws[lw_k+4][lw_j]=b4.x; Ws[lw_k+5][lw_j]=b4.y; Ws[lw_k+6][lw_j]=b4.z; Ws[lw_k+7][lw_j]=b4.w;
        }
        __syncthreads();
#pragma unroll
        for (int k = 0; k < 16; ++k) {
            float4 av = *(const float4*)&As[k][ty * 4];
            ull a0 = splat2(av.x), a1 = splat2(av.y), a2 = splat2(av.z), a3 = splat2(av.w);
            longlong2 b01 = *(const longlong2*)&Ws[k][tx * 8];
            longlong2 b23 = *(const longlong2*)&Ws[k][tx * 8 + 4];
            ffma2(acc[0][0], a0, (ull)b01.x); ffma2(acc[1][0], a1, (ull)b01.x);
            ffma2(acc[2][0], a2, (ull)b01.x); ffma2(acc[3][0], a3, (ull)b01.x);
            ffma2(acc[0][1], a0, (ull)b01.y); ffma2(acc[1][1], a1, (ull)b01.y);
            ffma2(acc[2][1], a2, (ull)b01.y); ffma2(acc[3][1], a3, (ull)b01.y);
            ffma2(acc[0][2], a0, (ull)b23.x); ffma2(acc[1][2], a1, (ull)b23.x);
            ffma2(acc[2][2], a2, (ull)b23.x); ffma2(acc[3][2], a3, (ull)b23.x);
            ffma2(acc[0][3], a0, (ull)b23.y); ffma2(acc[1][3], a1, (ull)b23.y);
            ffma2(acc[2][3], a2, (ull)b23.y); ffma2(acc[3][3], a3, (ull)b23.y);
        }
        __syncthreads();
    }
#pragma unroll
    for (int p = 0; p < 4; ++p) {
        float2 c0v = unpack2(acc[p][0]), c1v = unpack2(acc[p][1]);
        float2 c2v = unpack2(acc[p][2]), c3v = unpack2(acc[p][3]);
        float* dst = g_xw + (size_t)(r0 + ty * 4 + p) * 2048 + g0 + tx * 8;
        *(float4*)dst       = make_float4(c0v.x, c0v.y, c1v.x, c1v.y);
        *(float4*)(dst + 4) = make_float4(c2v.x, c2v.y, c3v.x, c3v.y);
    }
}

// ---------------- persistent encoder recurrence ----------------
__device__ __forceinline__ void gridbar(int step) {
    __syncthreads();
    if (threadIdx.x == 0) {
        __threadfence();
        unsigned target = 128u * (unsigned)(step + 1);
        atomicAdd(&g_barCnt, 1u);
        while (atomicAdd(&g_barCnt, 0u) < target) { }
    }
    __syncthreads();
}

__global__ void __launch_bounds__(256) enc_persist(
    const float* __restrict__ Whh, const float* __restrict__ bias)
{
    extern __shared__ char esm_raw[];
    ull*   sWif = (ull*)esm_raw;
    ull*   sWgo = sWif + 512 * 4;
    float* h_sm = (float*)(sWgo + 512 * 4);

    const int tid = threadIdx.x;
    const int hc0 = blockIdx.x * 4;
    {
        int hc = tid >> 6;
        int kb = (tid & 63) * 8;
        const float* wi = Whh + (size_t)(0 * 512 + hc0 + hc) * 512;
        const float* wf = Whh + (size_t)(1 * 512 + hc0 + hc) * 512;
        const float* wg = Whh + (size_t)(2 * 512 + hc0 + hc) * 512;
        const float* wo = Whh + (size_t)(3 * 512 + hc0 + hc) * 512;
#pragma unroll
        for (int k = kb; k < kb + 8; ++k) {
            sWif[k * 4 + hc] = pack2(wi[k], wf[k]);
            sWgo[k * 4 + hc] = pack2(wg[k], wo[k]);
        }
    }
    const int r  = tid >> 2;
    const int hc = tid & 3;
    const float bi = bias[0 * 512 + hc0 + hc];
    const float bf = bias[1 * 512 + hc0 + hc];
    const float bg = bias[2 * 512 + hc0 + hc];
    const float bo = bias[3 * 512 + hc0 + hc];
    float c = 0.f;
    __syncthreads();

    const int lr = tid & 63;
    const int lq = (tid >> 6) * 4;

    for (int t = 0; t < 64; ++t) {
        ull aif = 0ull, ago = 0ull;
        if (t > 0) {
            const float* hprev = g_hid + (size_t)(t - 1) * 64 * 512;
            for (int kc = 0; kc < 512; kc += 128) {
                {
                    const float* src = hprev + (size_t)lr * 512 + kc;
#pragma unroll
                    for (int q = lq; q < 128; q += 16)
                        *(float4*)&h_sm[lr * 132 + q] = *(const float4*)(src + q);
                }
                __syncthreads();
#pragma unroll
                for (int kq = 0; kq < 128; kq += 4) {
                    float4 a = *(const float4*)&h_sm[r * 132 + kq];
                    ull a0 = splat2(a.x), a1 = splat2(a.y), a2 = splat2(a.z), a3 = splat2(a.w);
                    int kb2 = (kc + kq) * 4 + hc;
                    ffma2(aif, a0, sWif[kb2 + 0]);  ffma2(ago, a0, sWgo[kb2 + 0]);
                    ffma2(aif, a1, sWif[kb2 + 4]);  ffma2(ago, a1, sWgo[kb2 + 4]);
                    ffma2(aif, a2, sWif[kb2 + 8]);  ffma2(ago, a2, sWgo[kb2 + 8]);
                    ffma2(aif, a3, sWif[kb2 + 12]); ffma2(ago, a3, sWgo[kb2 + 12]);
                }
                __syncthreads();
            }
        }
        const float* xw = g_xw + ((size_t)t * 64 + r) * 2048;
        float2 vif = unpack2(aif), vgo = unpack2(ago);
        float gi = vif.x + xw[0 * 512 + hc0 + hc] + bi;
        float gf = vif.y + xw[1 * 512 + hc0 + hc] + bf;
        float gg = vgo.x + xw[2 * 512 + hc0 + hc] + bg;
        float go = vgo.y + xw[3 * 512 + hc0 + hc] + bo;
        c = sigm_(gf) * c + sigm_(gi) * tanhf(gg);
        float h = sigm_(go) * tanhf(c);
        g_hid[((size_t)t * 64 + r) * 512 + hc0 + hc] = h;
        if (t < 63) gridbar(t);
    }
}

// ---------------- decoder h0 ----------------
__global__ void h0_init_kernel() {
    int i = blockIdx.x * blockDim.x + threadIdx.x;
    int h = i & 511;
    int rr = i >> 9;
    int r = rr & 2047, dir = rr >> 11;
    int t = r >> 5, b = r & 31;
    g_h0[i] = g_hid[((size_t)t * 64 + dir * 32 + b) * 512 + h];
}

// ---------------- decoder LSTM step ----------------
__global__ void __launch_bounds__(256) dec_step(
    const float* __restrict__ emb,
    const float* __restrict__ Wih0, const float* __restrict__ Whh0, const float* __restrict__ b0,
    const float* __restrict__ Wih1, const float* __restrict__ Whh1, const float* __restrict__ b1,
    int step)
{
    const int dir = blockIdx.z;
    const float* Wih = dir ? Wih1 : Wih0;
    const float* Whh = dir ? Whh1 : Whh0;
    const float* bias = dir ? b1 : b0;

    const int* tok = g_decTok + (dir * 4 + step) * 2048;
    const float* h_in = step ? g_hs + ((size_t)(dir * 4 + step - 1)) * 2048 * 512
                             : g_h0 + (size_t)dir * 2048 * 512;
    const float* c_in = step ? g_dc + (size_t)((step - 1) & 1) * DCBUF + (size_t)dir * 2048 * 512
                             : g_h0 + (size_t)dir * 2048 * 512;
    float* h_out = g_hs + ((size_t)(dir * 4 + step)) * 2048 * 512;
    __nv_bfloat16* hb_out = g_hsb + ((size_t)(dir * 4 + step)) * 2048 * 512;
    float* c_out = g_dc + (size_t)(step & 1) * DCBUF + (size_t)dir * 2048 * 512;

    __shared__ __align__(16) float As[16][64];
    __shared__ __align__(16) float Ws[16][128];
    __shared__ float Gs[64][130];

    const int tid = threadIdx.x;
    const int r0 = blockIdx.x * 64;
    const int c0h = blockIdx.y * 32;
    const int tx = tid & 15, ty = tid >> 4;

    const int la_r = tid & 63;
    const int la_q = (tid >> 6) * 4;
    const int mytok = tok[r0 + la_r];
    const float* aE = emb + (size_t)mytok * 256;
    const float* aH = h_in + (size_t)(r0 + la_r) * 512 - 256;

    const int lw_j = tid >> 1;
    const int lw_k = (tid & 1) * 8;
    const int wrow = (lw_j >> 5) * 512 + c0h + (lw_j & 31);
    const float* wI = Wih + (size_t)wrow * 256;
    const float* wH = Whh + (size_t)wrow * 512 - 256;

    ull acc[4][4];
#pragma unroll
    for (int p = 0; p < 4; ++p)
#pragma unroll
        for (int c = 0; c < 4; ++c) acc[p][c] = 0ull;

    for (int k0 = 0; k0 < 768; k0 += 16) {
        {
            const float* s = (k0 < 256 ? aE : aH) + k0 + la_q;
            float4 v = *(const float4*)s;
            As[la_q+0][la_r]=v.x; As[la_q+1][la_r]=v.y; As[la_q+2][la_r]=v.z; As[la_q+3][la_r]=v.w;
        }
        {
            const float* s = (k0 < 256 ? wI : wH) + k0 + lw_k;
            float4 a4 = *(const float4*)s;
            float4 b4 = *(const float4*)(s + 4);
            Ws[lw_k+0][lw_j]=a4.x; Ws[lw_k+1][lw_j]=a4.y; Ws[lw_k+2][lw_j]=a4.z; Ws[lw_k+3][lw_j]=a4.w;
            Ws[lw_k+4][lw_j]=b4.x; Ws[lw_k+5][lw_j]=b4.y; Ws[lw_k+6][lw_j]=b4.z; Ws[lw_k+7][lw_j]=b4.w;
        }
        __syncthreads();
#pragma unroll
        for (int k = 0; k < 16; ++k) {
            float4 av = *(const float4*)&As[k][ty * 4];
            ull a0 = splat2(av.x), a1 = splat2(av.y), a2 = splat2(av.z), a3 = splat2(av.w);
            longlong2 b01 = *(const longlong2*)&Ws[k][tx * 8];
            longlong2 b23 = *(const longlong2*)&Ws[k][tx * 8 + 4];
            ffma2(acc[0][0], a0, (ull)b01.x); ffma2(acc[1][0], a1, (ull)b01.x);
            ffma2(acc[2][0], a2, (ull)b01.x); ffma2(acc[3][0], a3, (ull)b01.x);
            ffma2(acc[0][1], a0, (ull)b01.y); ffma2(acc[1][1], a1, (ull)b01.y);
            ffma2(acc[2][1], a2, (ull)b01.y); ffma2(acc[3][1], a3, (ull)b01.y);
            ffma2(acc[0][2], a0, (ull)b23.x); ffma2(acc[1][2], a1, (ull)b23.x);
            ffma2(acc[2][2], a2, (ull)b23.x); ffma2(acc[3][2], a3, (ull)b23.x);
            ffma2(acc[0][3], a0, (ull)b23.y); ffma2(acc[1][3], a1, (ull)b23.y);
            ffma2(acc[2][3], a2, (ull)b23.y); ffma2(acc[3][3], a3, (ull)b23.y);
        }
        __syncthreads();
    }

#pragma unroll
    for (int cp = 0; cp < 4; ++cp) {
        float2 v[4];
#pragma unroll
        for (int p = 0; p < 4; ++p) v[p] = unpack2(acc[p][cp]);
        int j0 = tx * 8 + 2 * cp;
#pragma unroll
        for (int u = 0; u < 2; ++u) {
            int j = j0 + u;
            float bb = bias[(j >> 5) * 512 + c0h + (j & 31)];
#pragma unroll
            for (int p = 0; p < 4; ++p)
                Gs[ty * 4 + p][j] = (u == 0 ? v[p].x : v[p].y) + bb;
        }
    }
    __syncthreads();

    {
        int row = tid >> 2;
        int hq = (tid & 3) * 8;
        size_t base = (size_t)(r0 + row) * 512 + c0h + hq;
#pragma unroll
        for (int q = 0; q < 8; ++q) {
            int hcj = hq + q;
            float gi = Gs[row][hcj];
            float gf = Gs[row][32 + hcj];
            float gg = Gs[row][64 + hcj];
            float go = Gs[row][96 + hcj];
            float cp2 = c_in[base + q];
            float cc = sigm_(gf) * cp2 + sigm_(gi) * tanhf(gg);
            float hh = sigm_(go) * tanhf(cc);
            c_out[base + q] = cc;
            h_out[base + q] = hh;
            hb_out[base + q] = __float2bfloat16(hh);
        }
    }
}

// ---------------- mma.sync projection + online logsumexp ----------------
// grid 128: dir = bx>>6, m0 = (bx&63)*128. 256 threads = 8 warps (4 m x 2 n).
// A (128x512 bf16) smem-resident; B streamed in 128x64 chunks; warp tile 32x64.
#define PA_STRIDE 520   // bf16 elems per A row (1040 B)
#define PB_STRIDE 72    // bf16 elems per B row (144 B)
#define SMP_A 0
#define SMP_B 133120
#define SMP_HB 151552
#define SMP_RED 152064
#define SMP_TOTAL 156160
__global__ void __launch_bounds__(256) proj_mma(
    const float* __restrict__ hb0, const float* __restrict__ hb1)
{
    extern __shared__ char sm[];
    const uint32_t base = smem_u32(sm);
    float* sHb  = (float*)(sm + SMP_HB);
    float* redM = (float*)(sm + SMP_RED);
    float* redS = redM + 256;
    float* redC = redS + 256;
    float* redP = redC + 256;

    const int tid = threadIdx.x, lane = tid & 31, warp = tid >> 5;
    const int wm = warp >> 1, wn = warp & 1;
    const int dir = blockIdx.x >> 6;
    const int m0 = (blockIdx.x & 63) * 128;
    const float* hb = dir ? hb1 : hb0;

    // load resident A tile (128 rows x 512 k)
    {
        const __nv_bfloat16* Asrc = g_hsb + (size_t)dir * 4 * 2048 * 512 + (size_t)m0 * 512;
        for (int it = tid; it < 8192; it += 256) {
            int row = it >> 6, k = (it & 63) * 8;
            *(uint4*)(sm + SMP_A + row * 1040 + k * 2) =
                *(const uint4*)(Asrc + (size_t)row * 512 + k);
        }
    }

    // per-thread row state: st = mf*2+half -> row wm*32 + mf*16 + half*8 + lane/4
    float m_[4], s_[4], gch_[4], gp_[4];
    int ytok[4];
#pragma unroll
    for (int st = 0; st < 4; ++st) {
        m_[st] = NEGF; s_[st] = 0.f; gch_[st] = 0.f; gp_[st] = 0.f;
        int rl = wm * 32 + (st >> 1) * 16 + (st & 1) * 8 + (lane >> 2);
        int rg = m0 + rl;
        int s = rg >> 11, r = rg & 2047;
        ytok[st] = (s < 3) ? g_segs[(dir * 2048 + r) * 3 + s] : 0;
    }

    // precomputed ldmatrix lane addresses
    const uint32_t aAddr0 = base + SMP_A + (uint32_t)((wm * 32 + (lane & 15)) * 1040 + ((lane >> 4) * 8) * 2);
    const int laneN = ((lane >> 4) << 3) + (lane & 7);
    const int laneK = ((lane >> 3) & 1) * 8;
    const uint32_t bAddr0 = base + SMP_B + (uint32_t)((wn * 64 + laneN) * 144 + laneK * 2);

    for (int nc = 0; nc < 63; ++nc) {
        __syncthreads();
        if (tid < 128) {
            int v = nc * 128 + tid;
            sHb[tid] = (v < 8000) ? hb[v] : 0.f;
        }
        float acc[2][8][4];
#pragma unroll
        for (int mf = 0; mf < 2; ++mf)
#pragma unroll
            for (int nf = 0; nf < 8; ++nf)
#pragma unroll
                for (int e = 0; e < 4; ++e) acc[mf][nf][e] = 0.f;

        for (int kc = 0; kc < 8; ++kc) {
            __syncthreads();
            {   // load B chunk [128 n][64 k]
                const __nv_bfloat16* Bsrc = g_hWb + (size_t)dir * 8064 * 512
                                            + (size_t)(nc * 128) * 512 + kc * 64;
                int n = tid >> 1;
                int kq0 = (tid & 1) * 4;
#pragma unroll
                for (int q = 0; q < 4; ++q) {
                    int k = (kq0 + q) * 8;
                    *(uint4*)(sm + SMP_B + n * 144 + k * 2) =
                        *(const uint4*)(Bsrc + (size_t)n * 512 + k);
                }
            }
            __syncthreads();
#pragma unroll
            for (int k16 = 0; k16 < 4; ++k16) {
                int kabs = kc * 64 + k16 * 16;
                uint32_t a[2][4];
                ldsm4(a[0], aAddr0 + kabs * 2);
                ldsm4(a[1], aAddr0 + 16 * 1040 + kabs * 2);
                uint32_t b[4][4];
#pragma unroll
                for (int ng = 0; ng < 4; ++ng)
                    ldsm4(b[ng], bAddr0 + ng * 16 * 144 + k16 * 32);
#pragma unroll
                for (int mf = 0; mf < 2; ++mf)
#pragma unroll
                    for (int ng = 0; ng < 4; ++ng) {
                        mma_bf16(acc[mf][ng * 2],     a[mf], &b[ng][0]);
                        mma_bf16(acc[mf][ng * 2 + 1], a[mf], &b[ng][2]);
                    }
            }
        }
        // epilogue: bias + lse + gathers
#pragma unroll
        for (int mf = 0; mf < 2; ++mf)
#pragma unroll
            for (int nf = 0; nf < 8; ++nf) {
                int li = wn * 64 + nf * 8 + 2 * (lane & 3);
                int col0 = nc * 128 + li;
                float b0 = sHb[li], b1 = sHb[li + 1];
#pragma unroll
                for (int e = 0; e < 4; ++e) {
                    int col = col0 + (e & 1);
                    int st = mf * 2 + (e >> 1);
                    if (col < 8000) {
                        float lg = acc[mf][nf][e] + ((e & 1) ? b1 : b0);
                        lse_upd(lg, m_[st], s_[st]);
                        if (col == ytok[st]) gch_[st] = lg;
                        if (col == 0)        gp_[st]  = lg;
                    }
                }
            }
    }

    // reduce across the 4 lanes of each row group
#pragma unroll
    for (int st = 0; st < 4; ++st) {
#pragma unroll
        for (int off = 1; off <= 2; off <<= 1) {
            float om = __shfl_xor_sync(0xffffffffu, m_[st], off);
            float os = __shfl_xor_sync(0xffffffffu, s_[st], off);
            float M = fmaxf(m_[st], om);
            s_[st] = s_[st] * __expf(m_[st] - M) + os * __expf(om - M);
            m_[st] = M;
            gch_[st] += __shfl_xor_sync(0xffffffffu, gch_[st], off);
            gp_[st]  += __shfl_xor_sync(0xffffffffu, gp_[st], off);
        }
    }
    __syncthreads();
    if ((lane & 3) == 0) {
#pragma unroll
        for (int st = 0; st < 4; ++st) {
            int rl = wm * 32 + (st >> 1) * 16 + (st & 1) * 8 + (lane >> 2);
            int idx = wn * 128 + rl;
            redM[idx] = m_[st]; redS[idx] = s_[st];
            redC[idx] = gch_[st]; redP[idx] = gp_[st];
        }
    }
    __syncthreads();
    if (tid < 128) {
        float mA = redM[tid], sA = redS[tid];
        float mB = redM[128 + tid], sB = redS[128 + tid];
        float M = fmaxf(mA, mB);
        float S = sA * __expf(mA - M) + sB * __expf(mB - M);
        int rg = m0 + tid;
        int s = rg >> 11, r = rg & 2047;
        int idx = (dir * 4 + s) * 2048 + r;
        g_logZ[idx] = M + logf(S);
        g_gch[idx]  = redC[tid] + redC[128 + tid];
        g_gp[idx]   = redP[tid] + redP[128 + tid];
    }
}

// ---------------- final DP ----------------
__device__ __forceinline__ float seg_score(int dir, int t, int l, int b) {
    int r = t * 32 + b;
    float acc = 0.f;
    for (int s = 0; s <= l; ++s) {
        int idx = (dir * 4 + s) * 2048 + r;
        acc += g_gch[idx] - g_logZ[idx];
    }
    int idx = (dir * 4 + l + 1) * 2048 + r;
    acc += g_gp[idx] - g_logZ[idx];
    return acc;
}

__global__ void dp_kernel(float* __restrict__ out) {
    int b = threadIdx.x;
    float buf0 = 0.f, buf1 = NEGF, buf2 = NEGF;
    for (int e = 0; e < 64; ++e) {
        float p[3];
#pragma unroll
        for (int l = 0; l < 3; ++l) {
            int start = e - l;
            p[l] = (start >= 0)
                 ? seg_score(0, start, l, b) + seg_score(1, 63 - e, l, b)
                 : NEGF;
        }
        float x0 = buf0 + p[0], x1 = buf1 + p[1], x2 = buf2 + p[2];
        float M = fmaxf(x0, fmaxf(x1, x2));
        float tot = M + logf(__expf(x0 - M) + __expf(x1 - M) + __expf(x2 - M));
        buf2 = buf1; buf1 = buf0; buf0 = tot;
    }
    float v = buf0;
#pragma unroll
    for (int off = 16; off; off >>= 1) v += __shfl_xor_sync(0xffffffffu, v, off);
    if (b == 0) out[0] = -v / 32.f;
}

// ---------------- launch ----------------
extern "C" void kernel_launch(void* const* d_in, const int* in_sizes, int n_in,
                              void* d_out, int out_size) {
    const int*   sent = (const int*)  d_in[0];
    const float* emb  = (const float*)d_in[1];
    const float* eWih = (const float*)d_in[2];
    const float* eWhh = (const float*)d_in[3];
    const float* eb   = (const float*)d_in[4];
    const float* fWih = (const float*)d_in[5];
    const float* fWhh = (const float*)d_in[6];
    const float* fb   = (const float*)d_in[7];
    const float* fhW  = (const float*)d_in[8];
    const float* fhb  = (const float*)d_in[9];
    const float* bWih = (const float*)d_in[10];
    const float* bWhh = (const float*)d_in[11];
    const float* bb   = (const float*)d_in[12];
    const float* bhW  = (const float*)d_in[13];
    const float* bhb  = (const float*)d_in[14];

    cudaFuncSetAttribute(enc_persist, cudaFuncAttributeMaxDynamicSharedMemorySize, 66560);
    cudaFuncSetAttribute(proj_mma,    cudaFuncAttributeMaxDynamicSharedMemorySize, SMP_TOTAL);

    prep_kernel<<<64, 256>>>(sent);
    cvt_hw<<<16128, 512>>>(fhW, bhW);
    xw_gemm<<<dim3(64, 16), 256>>>(emb, eWih);
    enc_persist<<<128, 256, 66560>>>(eWhh, eb);
    h0_init_kernel<<<8192, 256>>>();
    for (int s = 0; s < 4; ++s)
        dec_step<<<dim3(32, 16, 2), 256>>>(emb, fWih, fWhh, fb, bWih, bWhh, bb, s);
    proj_mma<<<128, 256, SMP_TOTAL>>>(fhb, bhb);
    dp_kernel<<<1, 32>>>((float*)d_out);
}

// round 6
// speedup vs baseline: 5.6131x; 1.5917x over previous
#include <cuda_runtime.h>
#include <cuda_bf16.h>
#include <cstddef>
#include <cstdint>

typedef unsigned long long ull;
#define NEGF (-1e30f)

// ---------------- scratch ----------------
#define DCBUF (2*2048*512)
__device__ int   g_encTok[64 * 64];
__device__ int   g_segs[2 * 2048 * 3];
__device__ int   g_decTok[2 * 4 * 2048];
__device__ float g_hid[64 * 64 * 512];
__device__ float g_xw[64 * 64 * 2048];
__device__ float g_h0[2 * 2048 * 512];
__device__ __nv_bfloat16 g_h0b[2 * 2048 * 512];
__device__ float g_dc[2 * DCBUF];
__device__ __nv_bfloat16 g_hsb[2 * 4 * 2048 * 512];   // bf16 decoder h
__device__ __nv_bfloat16 g_hWb[2 * 8064 * 512];       // bf16 hW, padded
__device__ __nv_bfloat16 g_embB[8000 * 256];          // bf16 embedding
__device__ __nv_bfloat16 g_Wp[2 * 2048 * 768];        // permuted decoder weights
__device__ float g_bp[2 * 2048];                      // permuted decoder bias
__device__ float g_logZ[2 * 4 * 2048];
__device__ float g_gch[2 * 4 * 2048];
__device__ float g_gp[2 * 4 * 2048];
__device__ unsigned g_barCnt;

// ---------------- helpers ----------------
__device__ __forceinline__ float sigm_(float x) { return 1.f / (1.f + __expf(-x)); }
__device__ __forceinline__ ull splat2(float b) {
    ull r; asm("mov.b64 %0, {%1, %1};" : "=l"(r) : "f"(b)); return r;
}
__device__ __forceinline__ ull pack2(float x, float y) {
    ull r; asm("mov.b64 %0, {%1, %2};" : "=l"(r) : "f"(x), "f"(y)); return r;
}
__device__ __forceinline__ void ffma2(ull &acc, ull a, ull b) {
    asm("fma.rn.f32x2 %0, %1, %2, %0;" : "+l"(acc) : "l"(a), "l"(b));
}
__device__ __forceinline__ float2 unpack2(ull v) {
    float2 r; asm("mov.b64 {%0, %1}, %2;" : "=f"(r.x), "=f"(r.y) : "l"(v)); return r;
}
__device__ __forceinline__ void lse_upd(float x, float &m, float &s) {
    float d = x - m;
    if (d > 0.f) { s = s * __expf(-d) + 1.f; m = x; }
    else         { s += __expf(d); }
}
__device__ __forceinline__ uint32_t smem_u32(const void* p) {
    uint32_t a;
    asm("{ .reg .u64 t; cvta.to.shared.u64 t, %1; cvt.u32.u64 %0, t; }" : "=r"(a) : "l"(p));
    return a;
}
__device__ __forceinline__ void ldsm4(uint32_t* r, uint32_t addr) {
    asm volatile("ldmatrix.sync.aligned.m8n8.x4.shared.b16 {%0,%1,%2,%3}, [%4];"
        : "=r"(r[0]), "=r"(r[1]), "=r"(r[2]), "=r"(r[3]) : "r"(addr));
}
__device__ __forceinline__ void mma_bf16(float* d, const uint32_t* a, const uint32_t* b) {
    asm volatile(
        "mma.sync.aligned.m16n8k16.row.col.f32.bf16.bf16.f32 "
        "{%0,%1,%2,%3}, {%4,%5,%6,%7}, {%8,%9}, {%0,%1,%2,%3};"
        : "+f"(d[0]), "+f"(d[1]), "+f"(d[2]), "+f"(d[3])
        : "r"(a[0]), "r"(a[1]), "r"(a[2]), "r"(a[3]), "r"(b[0]), "r"(b[1]));
}

// ---------------- prep ----------------
__global__ void prep_kernel(const int* __restrict__ sent) {
    int tid = blockIdx.x * blockDim.x + threadIdx.x;
    int nthr = gridDim.x * blockDim.x;
    if (tid == 0) g_barCnt = 0u;
    for (int i = tid; i < 64 * 64; i += nthr) {
        int t = i >> 6, n = i & 63;
        int v = 0;
        if (t > 0) {
            int b = n & 31;
            v = (n < 32) ? sent[b * 64 + t - 1] : sent[b * 64 + 64 - t];
        }
        g_encTok[i] = v;
    }
    for (int i = tid; i < 2 * 2048; i += nthr) {
        int dir = i >> 11, r = i & 2047;
        int t = r >> 5, b = r & 31;
        int sg[3];
#pragma unroll
        for (int w = 0; w < 3; ++w) {
            int p = min(t + w, 63);
            sg[w] = (dir == 0) ? sent[b * 64 + p] : sent[b * 64 + 63 - p];
            g_segs[i * 3 + w] = sg[w];
        }
        g_decTok[(dir * 4 + 0) * 2048 + r] = 0;
#pragma unroll
        for (int s2 = 1; s2 < 4; ++s2) g_decTok[(dir * 4 + s2) * 2048 + r] = sg[s2 - 1];
    }
}

// ---------------- converters ----------------
__global__ void cvt_hw(const float* __restrict__ hW0, const float* __restrict__ hW1) {
    size_t i = (size_t)blockIdx.x * blockDim.x + threadIdx.x;
    if (i >= 2ull * 8064 * 512) return;
    int dir = (int)(i / (8064ull * 512));
    size_t rem = i % (8064ull * 512);
    int row = (int)(rem >> 9), k = (int)(rem & 511);
    const float* w = dir ? hW1 : hW0;
    float v = (row < 8000) ? w[(size_t)row * 512 + k] : 0.f;
    g_hWb[i] = __float2bfloat16(v);
}

__global__ void cvt_dec(const float* __restrict__ emb,
                        const float* __restrict__ fWih, const float* __restrict__ fWhh,
                        const float* __restrict__ fb,
                        const float* __restrict__ bWih, const float* __restrict__ bWhh,
                        const float* __restrict__ bb_) {
    int tid = blockIdx.x * blockDim.x + threadIdx.x;
    int n = gridDim.x * blockDim.x;
    for (int i = tid; i < 8000 * 256; i += n) g_embB[i] = __float2bfloat16(emb[i]);
    for (int i = tid; i < 2 * 2048 * 768; i += n) {
        int dir = i / (2048 * 768);
        int rem = i % (2048 * 768);
        int j = rem / 768, k = rem % 768;
        int hc = j >> 2, g = j & 3;
        const float* Wih = dir ? bWih : fWih;
        const float* Whh = dir ? bWhh : fWhh;
        float v = (k < 256) ? Wih[(size_t)(g * 512 + hc) * 256 + k]
                            : Whh[(size_t)(g * 512 + hc) * 512 + (k - 256)];
        g_Wp[i] = __float2bfloat16(v);
    }
    for (int i = tid; i < 2 * 2048; i += n) {
        int dir = i >> 11, j = i & 2047;
        const float* b = dir ? bb_ : fb;
        g_bp[i] = b[(j & 3) * 512 + (j >> 2)];
    }
}

// ---------------- encoder x·Wih^T batched GEMM ----------------
__global__ void __launch_bounds__(256) xw_gemm(
    const float* __restrict__ emb, const float* __restrict__ Wih)
{
    __shared__ __align__(16) float As[16][64];
    __shared__ __align__(16) float Ws[16][128];
    const int tid = threadIdx.x;
    const int r0 = blockIdx.x * 64;
    const int g0 = blockIdx.y * 128;
    const int tx = tid & 15, ty = tid >> 4;
    const int la_r = tid & 63;
    const int la_q = (tid >> 6) * 4;
    const int mytok = g_encTok[r0 + la_r];
    const float* aE = emb + (size_t)mytok * 256;
    const int lw_j = tid >> 1;
    const int lw_k = (tid & 1) * 8;
    const float* wI = Wih + (size_t)(g0 + lw_j) * 256;

    ull acc[4][4];
#pragma unroll
    for (int p = 0; p < 4; ++p)
#pragma unroll
        for (int c = 0; c < 4; ++c) acc[p][c] = 0ull;

    for (int k0 = 0; k0 < 256; k0 += 16) {
        {
            float4 v = *(const float4*)(aE + k0 + la_q);
            As[la_q+0][la_r]=v.x; As[la_q+1][la_r]=v.y; As[la_q+2][la_r]=v.z; As[la_q+3][la_r]=v.w;
        }
        {
            const float* s = wI + k0 + lw_k;
            float4 a4 = *(const float4*)s;
            float4 b4 = *(const float4*)(s + 4);
            Ws[lw_k+0][lw_j]=a4.x; Ws[lw_k+1][lw_j]=a4.y; Ws[lw_k+2][lw_j]=a4.z; Ws[lw_k+3][lw_j]=a4.w;
            Ws[lw_k+4][lw_j]=b4.x; Ws[lw_k+5][lw_j]=b4.y; Ws[lw_k+6][lw_j]=b4.z; Ws[lw_k+7][lw_j]=b4.w;
        }
        __syncthreads();
#pragma unroll
        for (int k = 0; k < 16; ++k) {
            float4 av = *(const float4*)&As[k][ty * 4];
            ull a0 = splat2(av.x), a1 = splat2(av.y), a2 = splat2(av.z), a3 = splat2(av.w);
            longlong2 b01 = *(const longlong2*)&Ws[k][tx * 8];
            longlong2 b23 = *(const longlong2*)&Ws[k][tx * 8 + 4];
            ffma2(acc[0][0], a0, (ull)b01.x); ffma2(acc[1][0], a1, (ull)b01.x);
            ffma2(acc[2][0], a2, (ull)b01.x); ffma2(acc[3][0], a3, (ull)b01.x);
            ffma2(acc[0][1], a0, (ull)b01.y); ffma2(acc[1][1], a1, (ull)b01.y);
            ffma2(acc[2][1], a2, (ull)b01.y); ffma2(acc[3][1], a3, (ull)b01.y);
            ffma2(acc[0][2], a0, (ull)b23.x); ffma2(acc[1][2], a1, (ull)b23.x);
            ffma2(acc[2][2], a2, (ull)b23.x); ffma2(acc[3][2], a3, (ull)b23.x);
            ffma2(acc[0][3], a0, (ull)b23.y); ffma2(acc[1][3], a1, (ull)b23.y);
            ffma2(acc[2][3], a2, (ull)b23.y); ffma2(acc[3][3], a3, (ull)b23.y);
        }
        __syncthreads();
    }
#pragma unroll
    for (int p = 0; p < 4; ++p) {
        float2 c0v = unpack2(acc[p][0]), c1v = unpack2(acc[p][1]);
        float2 c2v = unpack2(acc[p][2]), c3v = unpack2(acc[p][3]);
        float* dst = g_xw + (size_t)(r0 + ty * 4 + p) * 2048 + g0 + tx * 8;
        *(float4*)dst       = make_float4(c0v.x, c0v.y, c1v.x, c1v.y);
        *(float4*)(dst + 4) = make_float4(c2v.x, c2v.y, c3v.x, c3v.y);
    }
}

// ---------------- persistent encoder recurrence ----------------
__device__ __forceinline__ void gridbar(int step) {
    __syncthreads();
    if (threadIdx.x == 0) {
        __threadfence();
        unsigned target = 128u * (unsigned)(step + 1);
        atomicAdd(&g_barCnt, 1u);
        while (atomicAdd(&g_barCnt, 0u) < target) { }
    }
    __syncthreads();
}

__global__ void __launch_bounds__(256) enc_persist(
    const float* __restrict__ Whh, const float* __restrict__ bias)
{
    extern __shared__ char esm_raw[];
    ull*   sWif = (ull*)esm_raw;
    ull*   sWgo = sWif + 512 * 4;
    float* h_sm = (float*)(sWgo + 512 * 4);

    const int tid = threadIdx.x;
    const int hc0 = blockIdx.x * 4;
    {
        int hc = tid >> 6;
        int kb = (tid & 63) * 8;
        const float* wi = Whh + (size_t)(0 * 512 + hc0 + hc) * 512;
        const float* wf = Whh + (size_t)(1 * 512 + hc0 + hc) * 512;
        const float* wg = Whh + (size_t)(2 * 512 + hc0 + hc) * 512;
        const float* wo = Whh + (size_t)(3 * 512 + hc0 + hc) * 512;
#pragma unroll
        for (int k = kb; k < kb + 8; ++k) {
            sWif[k * 4 + hc] = pack2(wi[k], wf[k]);
            sWgo[k * 4 + hc] = pack2(wg[k], wo[k]);
        }
    }
    const int r  = tid >> 2;
    const int hc = tid & 3;
    const float bi = bias[0 * 512 + hc0 + hc];
    const float bf = bias[1 * 512 + hc0 + hc];
    const float bg = bias[2 * 512 + hc0 + hc];
    const float bo = bias[3 * 512 + hc0 + hc];
    float c = 0.f;
    __syncthreads();

    const int lr = tid & 63;
    const int lq = (tid >> 6) * 4;

    for (int t = 0; t < 64; ++t) {
        ull aif = 0ull, ago = 0ull;
        if (t > 0) {
            const float* hprev = g_hid + (size_t)(t - 1) * 64 * 512;
            for (int kc = 0; kc < 512; kc += 128) {
                {
                    const float* src = hprev + (size_t)lr * 512 + kc;
#pragma unroll
                    for (int q = lq; q < 128; q += 16)
                        *(float4*)&h_sm[lr * 132 + q] = *(const float4*)(src + q);
                }
                __syncthreads();
#pragma unroll
                for (int kq = 0; kq < 128; kq += 4) {
                    float4 a = *(const float4*)&h_sm[r * 132 + kq];
                    ull a0 = splat2(a.x), a1 = splat2(a.y), a2 = splat2(a.z), a3 = splat2(a.w);
                    int kb2 = (kc + kq) * 4 + hc;
                    ffma2(aif, a0, sWif[kb2 + 0]);  ffma2(ago, a0, sWgo[kb2 + 0]);
                    ffma2(aif, a1, sWif[kb2 + 4]);  ffma2(ago, a1, sWgo[kb2 + 4]);
                    ffma2(aif, a2, sWif[kb2 + 8]);  ffma2(ago, a2, sWgo[kb2 + 8]);
                    ffma2(aif, a3, sWif[kb2 + 12]); ffma2(ago, a3, sWgo[kb2 + 12]);
                }
                __syncthreads();
            }
        }
        const float* xw = g_xw + ((size_t)t * 64 + r) * 2048;
        float2 vif = unpack2(aif), vgo = unpack2(ago);
        float gi = vif.x + xw[0 * 512 + hc0 + hc] + bi;
        float gf = vif.y + xw[1 * 512 + hc0 + hc] + bf;
        float gg = vgo.x + xw[2 * 512 + hc0 + hc] + bg;
        float go = vgo.y + xw[3 * 512 + hc0 + hc] + bo;
        c = sigm_(gf) * c + sigm_(gi) * tanhf(gg);
        float h = sigm_(go) * tanhf(c);
        g_hid[((size_t)t * 64 + r) * 512 + hc0 + hc] = h;
        if (t < 63) gridbar(t);
    }
}

// ---------------- decoder h0 (fp32 for c0, bf16 for GEMM A) ----------------
__global__ void h0_init_kernel() {
    int i = blockIdx.x * blockDim.x + threadIdx.x;
    int h = i & 511;
    int rr = i >> 9;
    int r = rr & 2047, dir = rr >> 11;
    int t = r >> 5, b = r & 31;
    float v = g_hid[((size_t)t * 64 + dir * 32 + b) * 512 + h];
    g_h0[i] = v;
    g_h0b[i] = __float2bfloat16(v);
}

// ---------------- decoder LSTM step via mma.sync ----------------
// grid (16 Mtiles, 16 Ntiles, 2 dirs), 256 thr = 8 warps (4m x 2n).
// Block tile: 128 rows x 128 permuted gate cols (= 32 hidden cols x 4 gates).
// K=768 streamed in 64-chunks. Epilogue: fused cell update.
#define SMD_A 0
#define SMD_B 18432
#define SMD_G 36864
#define SMD_BIAS (36864 + 68096)
#define SMD_TOTAL (SMD_BIAS + 512)
__global__ void __launch_bounds__(256) dec_mma(int step)
{
    extern __shared__ char sm[];
    const uint32_t base = smem_u32(sm);
    float* Gs = (float*)(sm + SMD_G);       // [128][133]
    float* sBias = (float*)(sm + SMD_BIAS); // [128]

    const int tid = threadIdx.x, lane = tid & 31, warp = tid >> 5;
    const int wm = warp >> 1, wn = warp & 1;
    const int dir = blockIdx.z;
    const int r0 = blockIdx.x * 128;
    const int n0 = blockIdx.y * 128;
    const int hc0 = blockIdx.y * 32;

    const int* tok = g_decTok + (dir * 4 + step) * 2048;
    const __nv_bfloat16* hb_in = (step == 0)
        ? g_h0b + (size_t)dir * 2048 * 512
        : g_hsb + ((size_t)(dir * 4 + step - 1)) * 2048 * 512;
    const float* c_in = step ? g_dc + (size_t)((step - 1) & 1) * DCBUF + (size_t)dir * 2048 * 512
                             : g_h0 + (size_t)dir * 2048 * 512;
    float* c_out = g_dc + (size_t)(step & 1) * DCBUF + (size_t)dir * 2048 * 512;
    __nv_bfloat16* hb_out = g_hsb + ((size_t)(dir * 4 + step)) * 2048 * 512;

    if (tid < 128) sBias[tid] = g_bp[dir * 2048 + n0 + tid];

    const int lrow = tid >> 1;
    const int lq0 = (tid & 1) * 4;
    const int myTok = tok[r0 + lrow];
    const __nv_bfloat16* pEmb = g_embB + (size_t)myTok * 256;
    const __nv_bfloat16* pH   = hb_in + (size_t)(r0 + lrow) * 512 - 256;
    const __nv_bfloat16* pW   = g_Wp + (size_t)dir * 2048 * 768 + (size_t)(n0 + lrow) * 768;

    float acc[2][8][4];
#pragma unroll
    for (int mf = 0; mf < 2; ++mf)
#pragma unroll
        for (int nf = 0; nf < 8; ++nf)
#pragma unroll
            for (int e = 0; e < 4; ++e) acc[mf][nf][e] = 0.f;

    const uint32_t aAddr0 = base + SMD_A + (uint32_t)((wm * 32 + (lane & 15)) * 144 + ((lane >> 4) * 8) * 2);
    const int laneN = ((lane >> 4) << 3) + (lane & 7);
    const int laneK = ((lane >> 3) & 1) * 8;
    const uint32_t bAddr0 = base + SMD_B + (uint32_t)((wn * 64 + laneN) * 144 + laneK * 2);

    for (int kc = 0; kc < 12; ++kc) {
        __syncthreads();
        const int kg = kc * 64;
        const __nv_bfloat16* aSrc = (kg < 256 ? pEmb : pH) + kg;
#pragma unroll
        for (int q = 0; q < 4; ++q) {
            int k = (lq0 + q) * 8;
            *(uint4*)(sm + SMD_A + lrow * 144 + k * 2) = *(const uint4*)(aSrc + k);
            *(uint4*)(sm + SMD_B + lrow * 144 + k * 2) = *(const uint4*)(pW + kg + k);
        }
        __syncthreads();
#pragma unroll
        for (int k16 = 0; k16 < 4; ++k16) {
            uint32_t a[2][4];
            ldsm4(a[0], aAddr0 + k16 * 32);
            ldsm4(a[1], aAddr0 + 16 * 144 + k16 * 32);
            uint32_t b[4][4];
#pragma unroll
            for (int ng = 0; ng < 4; ++ng)
                ldsm4(b[ng], bAddr0 + ng * 16 * 144 + k16 * 32);
#pragma unroll
            for (int mf = 0; mf < 2; ++mf)
#pragma unroll
                for (int ng = 0; ng < 4; ++ng) {
                    mma_bf16(acc[mf][ng * 2],     a[mf], &b[ng][0]);
                    mma_bf16(acc[mf][ng * 2 + 1], a[mf], &b[ng][2]);
                }
        }
    }
    __syncthreads();
    // stage gates (+bias) to smem
#pragma unroll
    for (int mf = 0; mf < 2; ++mf)
#pragma unroll
        for (int nf = 0; nf < 8; ++nf) {
            int colb = wn * 64 + nf * 8 + 2 * (lane & 3);
#pragma unroll
            for (int e = 0; e < 4; ++e) {
                int row = wm * 32 + mf * 16 + (e >> 1) * 8 + (lane >> 2);
                int col = colb + (e & 1);
                Gs[row * 133 + col] = acc[mf][nf][e] + sBias[col];
            }
        }
    __syncthreads();
    // fused cell update
    {
        int row = tid >> 1;
        int hq = (tid & 1) * 16;
        size_t gb = (size_t)(r0 + row) * 512 + hc0 + hq;
        const float* gr = Gs + row * 133 + hq * 4;
#pragma unroll
        for (int q = 0; q < 16; ++q) {
            float gi = gr[q * 4 + 0];
            float gf = gr[q * 4 + 1];
            float gg = gr[q * 4 + 2];
            float go = gr[q * 4 + 3];
            float cc = sigm_(gf) * c_in[gb + q] + sigm_(gi) * tanhf(gg);
            c_out[gb + q] = cc;
            hb_out[gb + q] = __float2bfloat16(sigm_(go) * tanhf(cc));
        }
    }
}

// ---------------- mma.sync projection + online logsumexp ----------------
#define SMP_A 0
#define SMP_B 133120
#define SMP_HB 151552
#define SMP_RED 152064
#define SMP_TOTAL 156160
__global__ void __launch_bounds__(256) proj_mma(
    const float* __restrict__ hb0, const float* __restrict__ hb1)
{
    extern __shared__ char sm[];
    const uint32_t base = smem_u32(sm);
    float* sHb  = (float*)(sm + SMP_HB);
    float* redM = (float*)(sm + SMP_RED);
    float* redS = redM + 256;
    float* redC = redS + 256;
    float* redP = redC + 256;

    const int tid = threadIdx.x, lane = tid & 31, warp = tid >> 5;
    const int wm = warp >> 1, wn = warp & 1;
    const int dir = blockIdx.x >> 6;
    const int m0 = (blockIdx.x & 63) * 128;
    const float* hb = dir ? hb1 : hb0;

    {
        const __nv_bfloat16* Asrc = g_hsb + (size_t)dir * 4 * 2048 * 512 + (size_t)m0 * 512;
        for (int it = tid; it < 8192; it += 256) {
            int row = it >> 6, k = (it & 63) * 8;
            *(uint4*)(sm + SMP_A + row * 1040 + k * 2) =
                *(const uint4*)(Asrc + (size_t)row * 512 + k);
        }
    }

    float m_[4], s_[4], gch_[4], gp_[4];
    int ytok[4];
#pragma unroll
    for (int st = 0; st < 4; ++st) {
        m_[st] = NEGF; s_[st] = 0.f; gch_[st] = 0.f; gp_[st] = 0.f;
        int rl = wm * 32 + (st >> 1) * 16 + (st & 1) * 8 + (lane >> 2);
        int rg = m0 + rl;
        int s = rg >> 11, r = rg & 2047;
        ytok[st] = (s < 3) ? g_segs[(dir * 2048 + r) * 3 + s] : 0;
    }

    const uint32_t aAddr0 = base + SMP_A + (uint32_t)((wm * 32 + (lane & 15)) * 1040 + ((lane >> 4) * 8) * 2);
    const int laneN = ((lane >> 4) << 3) + (lane & 7);
    const int laneK = ((lane >> 3) & 1) * 8;
    const uint32_t bAddr0 = base + SMP_B + (uint32_t)((wn * 64 + laneN) * 144 + laneK * 2);

    for (int nc = 0; nc < 63; ++nc) {
        __syncthreads();
        if (tid < 128) {
            int v = nc * 128 + tid;
            sHb[tid] = (v < 8000) ? hb[v] : 0.f;
        }
        float acc[2][8][4];
#pragma unroll
        for (int mf = 0; mf < 2; ++mf)
#pragma unroll
            for (int nf = 0; nf < 8; ++nf)
#pragma unroll
                for (int e = 0; e < 4; ++e) acc[mf][nf][e] = 0.f;

        for (int kc = 0; kc < 8; ++kc) {
            __syncthreads();
            {
                const __nv_bfloat16* Bsrc = g_hWb + (size_t)dir * 8064 * 512
                                            + (size_t)(nc * 128) * 512 + kc * 64;
                int n = tid >> 1;
                int kq0 = (tid & 1) * 4;
#pragma unroll
                for (int q = 0; q < 4; ++q) {
                    int k = (kq0 + q) * 8;
                    *(uint4*)(sm + SMP_B + n * 144 + k * 2) =
                        *(const uint4*)(Bsrc + (size_t)n * 512 + k);
                }
            }
            __syncthreads();
#pragma unroll
            for (int k16 = 0; k16 < 4; ++k16) {
                int kabs = kc * 64 + k16 * 16;
                uint32_t a[2][4];
                ldsm4(a[0], aAddr0 + kabs * 2);
                ldsm4(a[1], aAddr0 + 16 * 1040 + kabs * 2);
                uint32_t b[4][4];
#pragma unroll
                for (int ng = 0; ng < 4; ++ng)
                    ldsm4(b[ng], bAddr0 + ng * 16 * 144 + k16 * 32);
#pragma unroll
                for (int mf = 0; mf < 2; ++mf)
#pragma unroll
                    for (int ng = 0; ng < 4; ++ng) {
                        mma_bf16(acc[mf][ng * 2],     a[mf], &b[ng][0]);
                        mma_bf16(acc[mf][ng * 2 + 1], a[mf], &b[ng][2]);
                    }
            }
        }
#pragma unroll
        for (int mf = 0; mf < 2; ++mf)
#pragma unroll
            for (int nf = 0; nf < 8; ++nf) {
                int li = wn * 64 + nf * 8 + 2 * (lane & 3);
                int col0 = nc * 128 + li;
                float b0 = sHb[li], b1 = sHb[li + 1];
#pragma unroll
                for (int e = 0; e < 4; ++e) {
                    int col = col0 + (e & 1);
                    int st = mf * 2 + (e >> 1);
                    if (col < 8000) {
                        float lg = acc[mf][nf][e] + ((e & 1) ? b1 : b0);
                        lse_upd(lg, m_[st], s_[st]);
                        if (col == ytok[st]) gch_[st] = lg;
                        if (col == 0)        gp_[st]  = lg;
                    }
                }
            }
    }

#pragma unroll
    for (int st = 0; st < 4; ++st) {
#pragma unroll
        for (int off = 1; off <= 2; off <<= 1) {
            float om = __shfl_xor_sync(0xffffffffu, m_[st], off);
            float os = __shfl_xor_sync(0xffffffffu, s_[st], off);
            float M = fmaxf(m_[st], om);
            s_[st] = s_[st] * __expf(m_[st] - M) + os * __expf(om - M);
            m_[st] = M;
            gch_[st] += __shfl_xor_sync(0xffffffffu, gch_[st], off);
            gp_[st]  += __shfl_xor_sync(0xffffffffu, gp_[st], off);
        }
    }
    __syncthreads();
    if ((lane & 3) == 0) {
#pragma unroll
        for (int st = 0; st < 4; ++st) {
            int rl = wm * 32 + (st >> 1) * 16 + (st & 1) * 8 + (lane >> 2);
            int idx = wn * 128 + rl;
            redM[idx] = m_[st]; redS[idx] = s_[st];
            redC[idx] = gch_[st]; redP[idx] = gp_[st];
        }
    }
    __syncthreads();
    if (tid < 128) {
        float mA = redM[tid], sA = redS[tid];
        float mB = redM[128 + tid], sB = redS[128 + tid];
        float M = fmaxf(mA, mB);
        float S = sA * __expf(mA - M) + sB * __expf(mB - M);
        int rg = m0 + tid;
        int s = rg >> 11, r = rg & 2047;
        int idx = (dir * 4 + s) * 2048 + r;
        g_logZ[idx] = M + logf(S);
        g_gch[idx]  = redC[tid] + redC[128 + tid];
        g_gp[idx]   = redP[tid] + redP[128 + tid];
    }
}

// ---------------- final DP ----------------
__device__ __forceinline__ float seg_score(int dir, int t, int l, int b) {
    int r = t * 32 + b;
    float acc = 0.f;
    for (int s = 0; s <= l; ++s) {
        int idx = (dir * 4 + s) * 2048 + r;
        acc += g_gch[idx] - g_logZ[idx];
    }
    int idx = (dir * 4 + l + 1) * 2048 + r;
    acc += g_gp[idx] - g_logZ[idx];
    return acc;
}

__global__ void dp_kernel(float* __restrict__ out) {
    int b = threadIdx.x;
    float buf0 = 0.f, buf1 = NEGF, buf2 = NEGF;
    for (int e = 0; e < 64; ++e) {
        float p[3];
#pragma unroll
        for (int l = 0; l < 3; ++l) {
            int start = e - l;
            p[l] = (start >= 0)
                 ? seg_score(0, start, l, b) + seg_score(1, 63 - e, l, b)
                 : NEGF;
        }
        float x0 = buf0 + p[0], x1 = buf1 + p[1], x2 = buf2 + p[2];
        float M = fmaxf(x0, fmaxf(x1, x2));
        float tot = M + logf(__expf(x0 - M) + __expf(x1 - M) + __expf(x2 - M));
        buf2 = buf1; buf1 = buf0; buf0 = tot;
    }
    float v = buf0;
#pragma unroll
    for (int off = 16; off; off >>= 1) v += __shfl_xor_sync(0xffffffffu, v, off);
    if (b == 0) out[0] = -v / 32.f;
}

// ---------------- launch ----------------
extern "C" void kernel_launch(void* const* d_in, const int* in_sizes, int n_in,
                              void* d_out, int out_size) {
    const int*   sent = (const int*)  d_in[0];
    const float* emb  = (const float*)d_in[1];
    const float* eWih = (const float*)d_in[2];
    const float* eWhh = (const float*)d_in[3];
    const float* eb   = (const float*)d_in[4];
    const float* fWih = (const float*)d_in[5];
    const float* fWhh = (const float*)d_in[6];
    const float* fb   = (const float*)d_in[7];
    const float* fhW  = (const float*)d_in[8];
    const float* fhb  = (const float*)d_in[9];
    const float* bWih = (const float*)d_in[10];
    const float* bWhh = (const float*)d_in[11];
    const float* bb   = (const float*)d_in[12];
    const float* bhW  = (const float*)d_in[13];
    const float* bhb  = (const float*)d_in[14];

    cudaFuncSetAttribute(enc_persist, cudaFuncAttributeMaxDynamicSharedMemorySize, 66560);
    cudaFuncSetAttribute(dec_mma,     cudaFuncAttributeMaxDynamicSharedMemorySize, SMD_TOTAL);
    cudaFuncSetAttribute(proj_mma,    cudaFuncAttributeMaxDynamicSharedMemorySize, SMP_TOTAL);

    prep_kernel<<<64, 256>>>(sent);
    cvt_hw<<<16128, 512>>>(fhW, bhW);
    cvt_dec<<<1024, 256>>>(emb, fWih, fWhh, fb, bWih, bWhh, bb);
    xw_gemm<<<dim3(64, 16), 256>>>(emb, eWih);
    enc_persist<<<128, 256, 66560>>>(eWhh, eb);
    h0_init_kernel<<<8192, 256>>>();
    for (int s = 0; s < 4; ++s)
        dec_mma<<<dim3(16, 16, 2), 256, SMD_TOTAL>>>(s);
    proj_mma<<<128, 256, SMP_TOTAL>>>(fhb, bhb);
    dp_kernel<<<1, 32>>>((float*)d_out);
}

// round 7
// speedup vs baseline: 5.6132x; 1.0000x over previous
#include <cuda_runtime.h>
#include <cuda_bf16.h>
#include <cstddef>
#include <cstdint>

typedef unsigned long long ull;
#define NEGF (-1e30f)

// ---------------- scratch ----------------
#define DCBUF (2*2048*512)
__device__ int   g_encTok[64 * 64];
__device__ int   g_segs[2 * 2048 * 3];
__device__ int   g_decTok[2 * 4 * 2048];
__device__ float g_hid[64 * 64 * 512];
__device__ float g_xw[64 * 64 * 2048];
__device__ float g_h0[2 * 2048 * 512];
__device__ __nv_bfloat16 g_h0b[2 * 2048 * 512];
__device__ float g_dc[2 * DCBUF];
__device__ __nv_bfloat16 g_hsb[2 * 4 * 2048 * 512];   // bf16 decoder h
__device__ __nv_bfloat16 g_hWb[2 * 8064 * 512];       // bf16 hW, padded
__device__ __nv_bfloat16 g_embB[8000 * 256];          // bf16 embedding
__device__ __nv_bfloat16 g_Wp[2 * 2048 * 768];        // permuted decoder weights
__device__ float g_bp[2 * 2048];                      // permuted decoder bias
__device__ float g_logZ[2 * 4 * 2048];
__device__ float g_gch[2 * 4 * 2048];
__device__ float g_gp[2 * 4 * 2048];
__device__ unsigned g_barCnt;

// ---------------- helpers ----------------
__device__ __forceinline__ float sigm_(float x) { return 1.f / (1.f + __expf(-x)); }
__device__ __forceinline__ ull splat2(float b) {
    ull r; asm("mov.b64 %0, {%1, %1};" : "=l"(r) : "f"(b)); return r;
}
__device__ __forceinline__ ull pack2(float x, float y) {
    ull r; asm("mov.b64 %0, {%1, %2};" : "=l"(r) : "f"(x), "f"(y)); return r;
}
__device__ __forceinline__ void ffma2(ull &acc, ull a, ull b) {
    asm("fma.rn.f32x2 %0, %1, %2, %0;" : "+l"(acc) : "l"(a), "l"(b));
}
__device__ __forceinline__ float2 unpack2(ull v) {
    float2 r; asm("mov.b64 {%0, %1}, %2;" : "=f"(r.x), "=f"(r.y) : "l"(v)); return r;
}
__device__ __forceinline__ void lse_upd(float x, float &m, float &s) {
    float d = x - m;
    if (d > 0.f) { s = s * __expf(-d) + 1.f; m = x; }
    else         { s += __expf(d); }
}
__device__ __forceinline__ uint32_t smem_u32(const void* p) {
    uint32_t a;
    asm("{ .reg .u64 t; cvta.to.shared.u64 t, %1; cvt.u32.u64 %0, t; }" : "=r"(a) : "l"(p));
    return a;
}
__device__ __forceinline__ void ldsm4(uint32_t* r, uint32_t addr) {
    asm volatile("ldmatrix.sync.aligned.m8n8.x4.shared.b16 {%0,%1,%2,%3}, [%4];"
        : "=r"(r[0]), "=r"(r[1]), "=r"(r[2]), "=r"(r[3]) : "r"(addr));
}
__device__ __forceinline__ void mma_bf16(float* d, const uint32_t* a, const uint32_t* b) {
    asm volatile(
        "mma.sync.aligned.m16n8k16.row.col.f32.bf16.bf16.f32 "
        "{%0,%1,%2,%3}, {%4,%5,%6,%7}, {%8,%9}, {%0,%1,%2,%3};"
        : "+f"(d[0]), "+f"(d[1]), "+f"(d[2]), "+f"(d[3])
        : "r"(a[0]), "r"(a[1]), "r"(a[2]), "r"(a[3]), "r"(b[0]), "r"(b[1]));
}

// ---------------- prep ----------------
__global__ void prep_kernel(const int* __restrict__ sent) {
    int tid = blockIdx.x * blockDim.x + threadIdx.x;
    int nthr = gridDim.x * blockDim.x;
    if (tid == 0) g_barCnt = 0u;
    for (int i = tid; i < 64 * 64; i += nthr) {
        int t = i >> 6, n = i & 63;
        int v = 0;
        if (t > 0) {
            int b = n & 31;
            v = (n < 32) ? sent[b * 64 + t - 1] : sent[b * 64 + 64 - t];
        }
        g_encTok[i] = v;
    }
    for (int i = tid; i < 2 * 2048; i += nthr) {
        int dir = i >> 11, r = i & 2047;
        int t = r >> 5, b = r & 31;
        int sg[3];
#pragma unroll
        for (int w = 0; w < 3; ++w) {
            int p = min(t + w, 63);
            sg[w] = (dir == 0) ? sent[b * 64 + p] : sent[b * 64 + 63 - p];
            g_segs[i * 3 + w] = sg[w];
        }
        g_decTok[(dir * 4 + 0) * 2048 + r] = 0;
#pragma unroll
        for (int s2 = 1; s2 < 4; ++s2) g_decTok[(dir * 4 + s2) * 2048 + r] = sg[s2 - 1];
    }
}

// ---------------- converters ----------------
__global__ void cvt_hw(const float* __restrict__ hW0, const float* __restrict__ hW1) {
    size_t i = (size_t)blockIdx.x * blockDim.x + threadIdx.x;
    if (i >= 2ull * 8064 * 512) return;
    int dir = (int)(i / (8064ull * 512));
    size_t rem = i % (8064ull * 512);
    int row = (int)(rem >> 9), k = (int)(rem & 511);
    const float* w = dir ? hW1 : hW0;
    float v = (row < 8000) ? w[(size_t)row * 512 + k] : 0.f;
    g_hWb[i] = __float2bfloat16(v);
}

__global__ void cvt_dec(const float* __restrict__ emb,
                        const float* __restrict__ fWih, const float* __restrict__ fWhh,
                        const float* __restrict__ fb,
                        const float* __restrict__ bWih, const float* __restrict__ bWhh,
                        const float* __restrict__ bb_) {
    int tid = blockIdx.x * blockDim.x + threadIdx.x;
    int n = gridDim.x * blockDim.x;
    for (int i = tid; i < 8000 * 256; i += n) g_embB[i] = __float2bfloat16(emb[i]);
    for (int i = tid; i < 2 * 2048 * 768; i += n) {
        int dir = i / (2048 * 768);
        int rem = i % (2048 * 768);
        int j = rem / 768, k = rem % 768;
        int hc = j >> 2, g = j & 3;
        const float* Wih = dir ? bWih : fWih;
        const float* Whh = dir ? bWhh : fWhh;
        float v = (k < 256) ? Wih[(size_t)(g * 512 + hc) * 256 + k]
                            : Whh[(size_t)(g * 512 + hc) * 512 + (k - 256)];
        g_Wp[i] = __float2bfloat16(v);
    }
    for (int i = tid; i < 2 * 2048; i += n) {
        int dir = i >> 11, j = i & 2047;
        const float* b = dir ? bb_ : fb;
        g_bp[i] = b[(j & 3) * 512 + (j >> 2)];
    }
}

// ---------------- encoder x·Wih^T batched GEMM ----------------
__global__ void __launch_bounds__(256) xw_gemm(
    const float* __restrict__ emb, const float* __restrict__ Wih)
{
    __shared__ __align__(16) float As[16][64];
    __shared__ __align__(16) float Ws[16][128];
    const int tid = threadIdx.x;
    const int r0 = blockIdx.x * 64;
    const int g0 = blockIdx.y * 128;
    const int tx = tid & 15, ty = tid >> 4;
    const int la_r = tid & 63;
    const int la_q = (tid >> 6) * 4;
    const int mytok = g_encTok[r0 + la_r];
    const float* aE = emb + (size_t)mytok * 256;
    const int lw_j = tid >> 1;
    const int lw_k = (tid & 1) * 8;
    const float* wI = Wih + (size_t)(g0 + lw_j) * 256;

    ull acc[4][4];
#pragma unroll
    for (int p = 0; p < 4; ++p)
#pragma unroll
        for (int c = 0; c < 4; ++c) acc[p][c] = 0ull;

    for (int k0 = 0; k0 < 256; k0 += 16) {
        {
            float4 v = *(const float4*)(aE + k0 + la_q);
            As[la_q+0][la_r]=v.x; As[la_q+1][la_r]=v.y; As[la_q+2][la_r]=v.z; As[la_q+3][la_r]=v.w;
        }
        {
            const float* s = wI + k0 + lw_k;
            float4 a4 = *(const float4*)s;
            float4 b4 = *(const float4*)(s + 4);
            Ws[lw_k+0][lw_j]=a4.x; Ws[lw_k+1][lw_j]=a4.y; Ws[lw_k+2][lw_j]=a4.z; Ws[lw_k+3][lw_j]=a4.w;
            Ws[lw_k+4][lw_j]=b4.x; Ws[lw_k+5][lw_j]=b4.y; Ws[lw_k+6][lw_j]=b4.z; Ws[lw_k+7][lw_j]=b4.w;
        }
        __syncthreads();
#pragma unroll
        for (int k = 0; k < 16; ++k) {
            float4 av = *(const float4*)&As[k][ty * 4];
            ull a0 = splat2(av.x), a1 = splat2(av.y), a2 = splat2(av.z), a3 = splat2(av.w);
            longlong2 b01 = *(const longlong2*)&Ws[k][tx * 8];
            longlong2 b23 = *(const longlong2*)&Ws[k][tx * 8 + 4];
            ffma2(acc[0][0], a0, (ull)b01.x); ffma2(acc[1][0], a1, (ull)b01.x);
            ffma2(acc[2][0], a2, (ull)b01.x); ffma2(acc[3][0], a3, (ull)b01.x);
            ffma2(acc[0][1], a0, (ull)b01.y); ffma2(acc[1][1], a1, (ull)b01.y);
            ffma2(acc[2][1], a2, (ull)b01.y); ffma2(acc[3][1], a3, (ull)b01.y);
            ffma2(acc[0][2], a0, (ull)b23.x); ffma2(acc[1][2], a1, (ull)b23.x);
            ffma2(acc[2][2], a2, (ull)b23.x); ffma2(acc[3][2], a3, (ull)b23.x);
            ffma2(acc[0][3], a0, (ull)b23.y); ffma2(acc[1][3], a1, (ull)b23.y);
            ffma2(acc[2][3], a2, (ull)b23.y); ffma2(acc[3][3], a3, (ull)b23.y);
        }
        __syncthreads();
    }
#pragma unroll
    for (int p = 0; p < 4; ++p) {
        float2 c0v = unpack2(acc[p][0]), c1v = unpack2(acc[p][1]);
        float2 c2v = unpack2(acc[p][2]), c3v = unpack2(acc[p][3]);
        float* dst = g_xw + (size_t)(r0 + ty * 4 + p) * 2048 + g0 + tx * 8;
        *(float4*)dst       = make_float4(c0v.x, c0v.y, c1v.x, c1v.y);
        *(float4*)(dst + 4) = make_float4(c2v.x, c2v.y, c3v.x, c3v.y);
    }
}

// ---------------- persistent encoder recurrence ----------------
__device__ __forceinline__ void gridbar(int step) {
    __syncthreads();
    if (threadIdx.x == 0) {
        __threadfence();
        unsigned target = 128u * (unsigned)(step + 1);
        atomicAdd(&g_barCnt, 1u);
        while (atomicAdd(&g_barCnt, 0u) < target) { }
    }
    __syncthreads();
}

__global__ void __launch_bounds__(256) enc_persist(
    const float* __restrict__ Whh, const float* __restrict__ bias)
{
    extern __shared__ char esm_raw[];
    ull*   sWif = (ull*)esm_raw;
    ull*   sWgo = sWif + 512 * 4;
    float* h_sm = (float*)(sWgo + 512 * 4);

    const int tid = threadIdx.x;
    const int hc0 = blockIdx.x * 4;
    {
        int hc = tid >> 6;
        int kb = (tid & 63) * 8;
        const float* wi = Whh + (size_t)(0 * 512 + hc0 + hc) * 512;
        const float* wf = Whh + (size_t)(1 * 512 + hc0 + hc) * 512;
        const float* wg = Whh + (size_t)(2 * 512 + hc0 + hc) * 512;
        const float* wo = Whh + (size_t)(3 * 512 + hc0 + hc) * 512;
#pragma unroll
        for (int k = kb; k < kb + 8; ++k) {
            sWif[k * 4 + hc] = pack2(wi[k], wf[k]);
            sWgo[k * 4 + hc] = pack2(wg[k], wo[k]);
        }
    }
    const int r  = tid >> 2;
    const int hc = tid & 3;
    const float bi = bias[0 * 512 + hc0 + hc];
    const float bf = bias[1 * 512 + hc0 + hc];
    const float bg = bias[2 * 512 + hc0 + hc];
    const float bo = bias[3 * 512 + hc0 + hc];
    float c = 0.f;
    __syncthreads();

    const int lr = tid & 63;
    const int lq = (tid >> 6) * 4;

    for (int t = 0; t < 64; ++t) {
        ull aif = 0ull, ago = 0ull;
        if (t > 0) {
            const float* hprev = g_hid + (size_t)(t - 1) * 64 * 512;
            for (int kc = 0; kc < 512; kc += 128) {
                {
                    const float* src = hprev + (size_t)lr * 512 + kc;
#pragma unroll
                    for (int q = lq; q < 128; q += 16)
                        *(float4*)&h_sm[lr * 132 + q] = *(const float4*)(src + q);
                }
                __syncthreads();
#pragma unroll
                for (int kq = 0; kq < 128; kq += 4) {
                    float4 a = *(const float4*)&h_sm[r * 132 + kq];
                    ull a0 = splat2(a.x), a1 = splat2(a.y), a2 = splat2(a.z), a3 = splat2(a.w);
                    int kb2 = (kc + kq) * 4 + hc;
                    ffma2(aif, a0, sWif[kb2 + 0]);  ffma2(ago, a0, sWgo[kb2 + 0]);
                    ffma2(aif, a1, sWif[kb2 + 4]);  ffma2(ago, a1, sWgo[kb2 + 4]);
                    ffma2(aif, a2, sWif[kb2 + 8]);  ffma2(ago, a2, sWgo[kb2 + 8]);
                    ffma2(aif, a3, sWif[kb2 + 12]); ffma2(ago, a3, sWgo[kb2 + 12]);
                }
                __syncthreads();
            }
        }
        const float* xw = g_xw + ((size_t)t * 64 + r) * 2048;
        float2 vif = unpack2(aif), vgo = unpack2(ago);
        float gi = vif.x + xw[0 * 512 + hc0 + hc] + bi;
        float gf = vif.y + xw[1 * 512 + hc0 + hc] + bf;
        float gg = vgo.x + xw[2 * 512 + hc0 + hc] + bg;
        float go = vgo.y + xw[3 * 512 + hc0 + hc] + bo;
        c = sigm_(gf) * c + sigm_(gi) * tanhf(gg);
        float h = sigm_(go) * tanhf(c);
        g_hid[((size_t)t * 64 + r) * 512 + hc0 + hc] = h;
        if (t < 63) gridbar(t);
    }
}

// ---------------- decoder h0 (fp32 for c0, bf16 for GEMM A) ----------------
__global__ void h0_init_kernel() {
    int i = blockIdx.x * blockDim.x + threadIdx.x;
    int h = i & 511;
    int rr = i >> 9;
    int r = rr & 2047, dir = rr >> 11;
    int t = r >> 5, b = r & 31;
    float v = g_hid[((size_t)t * 64 + dir * 32 + b) * 512 + h];
    g_h0[i] = v;
    g_h0b[i] = __float2bfloat16(v);
}

// ---------------- decoder LSTM step via mma.sync ----------------
// grid (16 Mtiles, 16 Ntiles, 2 dirs), 256 thr = 8 warps (4m x 2n).
// Block tile: 128 rows x 128 permuted gate cols (= 32 hidden cols x 4 gates).
// K=768 streamed in 64-chunks. Epilogue: fused cell update.
#define SMD_A 0
#define SMD_B 18432
#define SMD_G 36864
#define SMD_BIAS (36864 + 68096)
#define SMD_TOTAL (SMD_BIAS + 512)
__global__ void __launch_bounds__(256) dec_mma(int step)
{
    extern __shared__ char sm[];
    const uint32_t base = smem_u32(sm);
    float* Gs = (float*)(sm + SMD_G);       // [128][133]
    float* sBias = (float*)(sm + SMD_BIAS); // [128]

    const int tid = threadIdx.x, lane = tid & 31, warp = tid >> 5;
    const int wm = warp >> 1, wn = warp & 1;
    const int dir = blockIdx.z;
    const int r0 = blockIdx.x * 128;
    const int n0 = blockIdx.y * 128;
    const int hc0 = blockIdx.y * 32;

    const int* tok = g_decTok + (dir * 4 + step) * 2048;
    const __nv_bfloat16* hb_in = (step == 0)
        ? g_h0b + (size_t)dir * 2048 * 512
        : g_hsb + ((size_t)(dir * 4 + step - 1)) * 2048 * 512;
    const float* c_in = step ? g_dc + (size_t)((step - 1) & 1) * DCBUF + (size_t)dir * 2048 * 512
                             : g_h0 + (size_t)dir * 2048 * 512;
    float* c_out = g_dc + (size_t)(step & 1) * DCBUF + (size_t)dir * 2048 * 512;
    __nv_bfloat16* hb_out = g_hsb + ((size_t)(dir * 4 + step)) * 2048 * 512;

    if (tid < 128) sBias[tid] = g_bp[dir * 2048 + n0 + tid];

    const int lrow = tid >> 1;
    const int lq0 = (tid & 1) * 4;
    const int myTok = tok[r0 + lrow];
    const __nv_bfloat16* pEmb = g_embB + (size_t)myTok * 256;
    const __nv_bfloat16* pH   = hb_in + (size_t)(r0 + lrow) * 512 - 256;
    const __nv_bfloat16* pW   = g_Wp + (size_t)dir * 2048 * 768 + (size_t)(n0 + lrow) * 768;

    float acc[2][8][4];
#pragma unroll
    for (int mf = 0; mf < 2; ++mf)
#pragma unroll
        for (int nf = 0; nf < 8; ++nf)
#pragma unroll
            for (int e = 0; e < 4; ++e) acc[mf][nf][e] = 0.f;

    const uint32_t aAddr0 = base + SMD_A + (uint32_t)((wm * 32 + (lane & 15)) * 144 + ((lane >> 4) * 8) * 2);
    const int laneN = ((lane >> 4) << 3) + (lane & 7);
    const int laneK = ((lane >> 3) & 1) * 8;
    const uint32_t bAddr0 = base + SMD_B + (uint32_t)((wn * 64 + laneN) * 144 + laneK * 2);

    for (int kc = 0; kc < 12; ++kc) {
        __syncthreads();
        const int kg = kc * 64;
        const __nv_bfloat16* aSrc = (kg < 256 ? pEmb : pH) + kg;
#pragma unroll
        for (int q = 0; q < 4; ++q) {
            int k = (lq0 + q) * 8;
            *(uint4*)(sm + SMD_A + lrow * 144 + k * 2) = *(const uint4*)(aSrc + k);
            *(uint4*)(sm + SMD_B + lrow * 144 + k * 2) = *(const uint4*)(pW + kg + k);
        }
        __syncthreads();
#pragma unroll
        for (int k16 = 0; k16 < 4; ++k16) {
            uint32_t a[2][4];
            ldsm4(a[0], aAddr0 + k16 * 32);
            ldsm4(a[1], aAddr0 + 16 * 144 + k16 * 32);
            uint32_t b[4][4];
#pragma unroll
            for (int ng = 0; ng < 4; ++ng)
                ldsm4(b[ng], bAddr0 + ng * 16 * 144 + k16 * 32);
#pragma unroll
            for (int mf = 0; mf < 2; ++mf)
#pragma unroll
                for (int ng = 0; ng < 4; ++ng) {
                    mma_bf16(acc[mf][ng * 2],     a[mf], &b[ng][0]);
                    mma_bf16(acc[mf][ng * 2 + 1], a[mf], &b[ng][2]);
                }
        }
    }
    __syncthreads();
    // stage gates (+bias) to smem
#pragma unroll
    for (int mf = 0; mf < 2; ++mf)
#pragma unroll
        for (int nf = 0; nf < 8; ++nf) {
            int colb = wn * 64 + nf * 8 + 2 * (lane & 3);
#pragma unroll
            for (int e = 0; e < 4; ++e) {
                int row = wm * 32 + mf * 16 + (e >> 1) * 8 + (lane >> 2);
                int col = colb + (e & 1);
                Gs[row * 133 + col] = acc[mf][nf][e] + sBias[col];
            }
        }
    __syncthreads();
    // fused cell update
    {
        int row = tid >> 1;
        int hq = (tid & 1) * 16;
        size_t gb = (size_t)(r0 + row) * 512 + hc0 + hq;
        const float* gr = Gs + row * 133 + hq * 4;
#pragma unroll
        for (int q = 0; q < 16; ++q) {
            float gi = gr[q * 4 + 0];
            float gf = gr[q * 4 + 1];
            float gg = gr[q * 4 + 2];
            float go = gr[q * 4 + 3];
            float cc = sigm_(gf) * c_in[gb + q] + sigm_(gi) * tanhf(gg);
            c_out[gb + q] = cc;
            hb_out[gb + q] = __float2bfloat16(sigm_(go) * tanhf(cc));
        }
    }
}

// ---------------- mma.sync projection + online logsumexp ----------------
#define SMP_A 0
#define SMP_B 133120
#define SMP_HB 151552
#define SMP_RED 152064
#define SMP_TOTAL 156160
__global__ void __launch_bounds__(256) proj_mma(
    const float* __restrict__ hb0, const float* __restrict__ hb1)
{
    extern __shared__ char sm[];
    const uint32_t base = smem_u32(sm);
    float* sHb  = (float*)(sm + SMP_HB);
    float* redM = (float*)(sm + SMP_RED);
    float* redS = redM + 256;
    float* redC = redS + 256;
    float* redP = redC + 256;

    const int tid = threadIdx.x, lane = tid & 31, warp = tid >> 5;
    const int wm = warp >> 1, wn = warp & 1;
    const int dir = blockIdx.x >> 6;
    const int m0 = (blockIdx.x & 63) * 128;
    const float* hb = dir ? hb1 : hb0;

    {
        const __nv_bfloat16* Asrc = g_hsb + (size_t)dir * 4 * 2048 * 512 + (size_t)m0 * 512;
        for (int it = tid; it < 8192; it += 256) {
            int row = it >> 6, k = (it & 63) * 8;
            *(uint4*)(sm + SMP_A + row * 1040 + k * 2) =
                *(const uint4*)(Asrc + (size_t)row * 512 + k);
        }
    }

    float m_[4], s_[4], gch_[4], gp_[4];
    int ytok[4];
#pragma unroll
    for (int st = 0; st < 4; ++st) {
        m_[st] = NEGF; s_[st] = 0.f; gch_[st] = 0.f; gp_[st] = 0.f;
        int rl = wm * 32 + (st >> 1) * 16 + (st & 1) * 8 + (lane >> 2);
        int rg = m0 + rl;
        int s = rg >> 11, r = rg & 2047;
        ytok[st] = (s < 3) ? g_segs[(dir * 2048 + r) * 3 + s] : 0;
    }

    const uint32_t aAddr0 = base + SMP_A + (uint32_t)((wm * 32 + (lane & 15)) * 1040 + ((lane >> 4) * 8) * 2);
    const int laneN = ((lane >> 4) << 3) + (lane & 7);
    const int laneK = ((lane >> 3) & 1) * 8;
    const uint32_t bAddr0 = base + SMP_B + (uint32_t)((wn * 64 + laneN) * 144 + laneK * 2);

    for (int nc = 0; nc < 63; ++nc) {
        __syncthreads();
        if (tid < 128) {
            int v = nc * 128 + tid;
            sHb[tid] = (v < 8000) ? hb[v] : 0.f;
        }
        float acc[2][8][4];
#pragma unroll
        for (int mf = 0; mf < 2; ++mf)
#pragma unroll
            for (int nf = 0; nf < 8; ++nf)
#pragma unroll
                for (int e = 0; e < 4; ++e) acc[mf][nf][e] = 0.f;

        for (int kc = 0; kc < 8; ++kc) {
            __syncthreads();
            {
                const __nv_bfloat16* Bsrc = g_hWb + (size_t)dir * 8064 * 512
                                            + (size_t)(nc * 128) * 512 + kc * 64;
                int n = tid >> 1;
                int kq0 = (tid & 1) * 4;
#pragma unroll
                for (int q = 0; q < 4; ++q) {
                    int k = (kq0 + q) * 8;
                    *(uint4*)(sm + SMP_B + n * 144 + k * 2) =
                        *(const uint4*)(Bsrc + (size_t)n * 512 + k);
                }
            }
            __syncthreads();
#pragma unroll
            for (int k16 = 0; k16 < 4; ++k16) {
                int kabs = kc * 64 + k16 * 16;
                uint32_t a[2][4];
                ldsm4(a[0], aAddr0 + kabs * 2);
                ldsm4(a[1], aAddr0 + 16 * 1040 + kabs * 2);
                uint32_t b[4][4];
#pragma unroll
                for (int ng = 0; ng < 4; ++ng)
                    ldsm4(b[ng], bAddr0 + ng * 16 * 144 + k16 * 32);
#pragma unroll
                for (int mf = 0; mf < 2; ++mf)
#pragma unroll
                    for (int ng = 0; ng < 4; ++ng) {
                        mma_bf16(acc[mf][ng * 2],     a[mf], &b[ng][0]);
                        mma_bf16(acc[mf][ng * 2 + 1], a[mf], &b[ng][2]);
                    }
            }
        }
#pragma unroll
        for (int mf = 0; mf < 2; ++mf)
#pragma unroll
            for (int nf = 0; nf < 8; ++nf) {
                int li = wn * 64 + nf * 8 + 2 * (lane & 3);
                int col0 = nc * 128 + li;
                float b0 = sHb[li], b1 = sHb[li + 1];
#pragma unroll
                for (int e = 0; e < 4; ++e) {
                    int col = col0 + (e & 1);
                    int st = mf * 2 + (e >> 1);
                    if (col < 8000) {
                        float lg = acc[mf][nf][e] + ((e & 1) ? b1 : b0);
                        lse_upd(lg, m_[st], s_[st]);
                        if (col == ytok[st]) gch_[st] = lg;
                        if (col == 0)        gp_[st]  = lg;
                    }
                }
            }
    }

#pragma unroll
    for (int st = 0; st < 4; ++st) {
#pragma unroll
        for (int off = 1; off <= 2; off <<= 1) {
            float om = __shfl_xor_sync(0xffffffffu, m_[st], off);
            float os = __shfl_xor_sync(0xffffffffu, s_[st], off);
            float M = fmaxf(m_[st], om);
            s_[st] = s_[st] * __expf(m_[st] - M) + os * __expf(om - M);
            m_[st] = M;
            gch_[st] += __shfl_xor_sync(0xffffffffu, gch_[st], off);
            gp_[st]  += __shfl_xor_sync(0xffffffffu, gp_[st], off);
        }
    }
    __syncthreads();
    if ((lane & 3) == 0) {
#pragma unroll
        for (int st = 0; st < 4; ++st) {
            int rl = wm * 32 + (st >> 1) * 16 + (st & 1) * 8 + (lane >> 2);
            int idx = wn * 128 + rl;
            redM[idx] = m_[st]; redS[idx] = s_[st];
            redC[idx] = gch_[st]; redP[idx] = gp_[st];
        }
    }
    __syncthreads();
    if (tid < 128) {
        float mA = redM[tid], sA = redS[tid];
        float mB = redM[128 + tid], sB = redS[128 + tid];
        float M = fmaxf(mA, mB);
        float S = sA * __expf(mA - M) + sB * __expf(mB - M);
        int rg = m0 + tid;
        int s = rg >> 11, r = rg & 2047;
        int idx = (dir * 4 + s) * 2048 + r;
        g_logZ[idx] = M + logf(S);
        g_gch[idx]  = redC[tid] + redC[128 + tid];
        g_gp[idx]   = redP[tid] + redP[128 + tid];
    }
}

// ---------------- final DP ----------------
__device__ __forceinline__ float seg_score(int dir, int t, int l, int b) {
    int r = t * 32 + b;
    float acc = 0.f;
    for (int s = 0; s <= l; ++s) {
        int idx = (dir * 4 + s) * 2048 + r;
        acc += g_gch[idx] - g_logZ[idx];
    }
    int idx = (dir * 4 + l + 1) * 2048 + r;
    acc += g_gp[idx] - g_logZ[idx];
    return acc;
}

__global__ void dp_kernel(float* __restrict__ out) {
    int b = threadIdx.x;
    float buf0 = 0.f, buf1 = NEGF, buf2 = NEGF;
    for (int e = 0; e < 64; ++e) {
        float p[3];
#pragma unroll
        for (int l = 0; l < 3; ++l) {
            int start = e - l;
            p[l] = (start >= 0)
                 ? seg_score(0, start, l, b) + seg_score(1, 63 - e, l, b)
                 : NEGF;
        }
        float x0 = buf0 + p[0], x1 = buf1 + p[1], x2 = buf2 + p[2];
        float M = fmaxf(x0, fmaxf(x1, x2));
        float tot = M + logf(__expf(x0 - M) + __expf(x1 - M) + __expf(x2 - M));
        buf2 = buf1; buf1 = buf0; buf0 = tot;
    }
    float v = buf0;
#pragma unroll
    for (int off = 16; off; off >>= 1) v += __shfl_xor_sync(0xffffffffu, v, off);
    if (b == 0) out[0] = -v / 32.f;
}

// ---------------- launch ----------------
extern "C" void kernel_launch(void* const* d_in, const int* in_sizes, int n_in,
                              void* d_out, int out_size) {
    const int*   sent = (const int*)  d_in[0];
    const float* emb  = (const float*)d_in[1];
    const float* eWih = (const float*)d_in[2];
    const float* eWhh = (const float*)d_in[3];
    const float* eb   = (const float*)d_in[4];
    const float* fWih = (const float*)d_in[5];
    const float* fWhh = (const float*)d_in[6];
    const float* fb   = (const float*)d_in[7];
    const float* fhW  = (const float*)d_in[8];
    const float* fhb  = (const float*)d_in[9];
    const float* bWih = (const float*)d_in[10];
    const float* bWhh = (const float*)d_in[11];
    const float* bb   = (const float*)d_in[12];
    const float* bhW  = (const float*)d_in[13];
    const float* bhb  = (const float*)d_in[14];

    cudaFuncSetAttribute(enc_persist, cudaFuncAttributeMaxDynamicSharedMemorySize, 66560);
    cudaFuncSetAttribute(dec_mma,     cudaFuncAttributeMaxDynamicSharedMemorySize, SMD_TOTAL);
    cudaFuncSetAttribute(proj_mma,    cudaFuncAttributeMaxDynamicSharedMemorySize, SMP_TOTAL);

    prep_kernel<<<64, 256>>>(sent);
    cvt_hw<<<16128, 512>>>(fhW, bhW);
    cvt_dec<<<1024, 256>>>(emb, fWih, fWhh, fb, bWih, bWhh, bb);
    xw_gemm<<<dim3(64, 16), 256>>>(emb, eWih);
    enc_persist<<<128, 256, 66560>>>(eWhh, eb);
    h0_init_kernel<<<8192, 256>>>();
    for (int s = 0; s < 4; ++s)
        dec_mma<<<dim3(16, 16, 2), 256, SMD_TOTAL>>>(s);
    proj_mma<<<128, 256, SMP_TOTAL>>>(fhb, bhb);
    dp_kernel<<<1, 32>>>((float*)d_out);
}